// round 1
// baseline (speedup 1.0000x reference)
#include <cuda_runtime.h>
#include <math.h>

#define Bn   128
#define Tn   256
#define DIN  512
#define Hn   1024
#define G4   4096   // 4*H
#define BRn  256

// Scratch (device globals: allocation-free kernel_launch)
__device__ float g_xg0[(size_t)Tn * Bn * G4];   // [T][B][4H] precomputed input projections + biases (layer 0)
__device__ float g_h0[2][Bn * Hn];              // double-buffered h for layer 0
__device__ float g_c0[Bn * Hn];
__device__ float g_h1[2][Bn * Hn];
__device__ float g_c1[Bn * Hn];

// ---------------------------------------------------------------------------
// Zero-init recurrent state (graph replays must be deterministic)
// ---------------------------------------------------------------------------
__global__ void init_state_kernel() {
    int i = blockIdx.x * blockDim.x + threadIdx.x;
    if (i < Bn * Hn) {
        g_h0[0][i] = 0.f;
        g_c0[i]    = 0.f;
        g_h1[0][i] = 0.f;
        g_c1[i]    = 0.f;
    }
}

// ---------------------------------------------------------------------------
// Precompute xg0[m][n] = sum_d X[b][t][d] * W_ih0[n][d] + b_ih0[n] + b_hh0[n]
// where m = t*B + b.  M=32768, N=4096, K=512.
// Tile: 128x64, 256 threads, 8x4 accum per thread.
// ---------------------------------------------------------------------------
__global__ void xg0_kernel(const float* __restrict__ X,
                           const float* __restrict__ W,
                           const float* __restrict__ b_ih,
                           const float* __restrict__ b_hh) {
    __shared__ float As[16][132];
    __shared__ float Bs[16][68];
    const int tid = threadIdx.x;
    const int ty = tid >> 4, tx = tid & 15;
    const int m0 = blockIdx.y * 128;
    const int n0 = blockIdx.x * 64;

    float acc[8][4];
#pragma unroll
    for (int r = 0; r < 8; r++)
#pragma unroll
        for (int c = 0; c < 4; c++) acc[r][c] = 0.f;

    for (int k0 = 0; k0 < DIN; k0 += 16) {
        // Load A tile: 128 rows x 16 k  (512 float4, 2 per thread)
#pragma unroll
        for (int i = 0; i < 2; i++) {
            int idx = tid + i * 256;
            int row = idx >> 2;
            int kq  = idx & 3;
            int m = m0 + row;
            int t = m / Bn, b = m % Bn;
            float4 v = *reinterpret_cast<const float4*>(
                X + ((size_t)b * Tn + t) * DIN + k0 + kq * 4);
            As[kq * 4 + 0][row] = v.x;
            As[kq * 4 + 1][row] = v.y;
            As[kq * 4 + 2][row] = v.z;
            As[kq * 4 + 3][row] = v.w;
        }
        // Load W tile: 64 rows x 16 k (256 float4, 1 per thread)
        {
            int row = tid >> 2;
            int kq  = tid & 3;
            float4 v = *reinterpret_cast<const float4*>(
                W + (size_t)(n0 + row) * DIN + k0 + kq * 4);
            Bs[kq * 4 + 0][row] = v.x;
            Bs[kq * 4 + 1][row] = v.y;
            Bs[kq * 4 + 2][row] = v.z;
            Bs[kq * 4 + 3][row] = v.w;
        }
        __syncthreads();
#pragma unroll
        for (int kk = 0; kk < 16; kk++) {
            float a[8], bv[4];
            *reinterpret_cast<float4*>(&a[0]) =
                *reinterpret_cast<const float4*>(&As[kk][ty * 8]);
            *reinterpret_cast<float4*>(&a[4]) =
                *reinterpret_cast<const float4*>(&As[kk][ty * 8 + 4]);
            *reinterpret_cast<float4*>(&bv[0]) =
                *reinterpret_cast<const float4*>(&Bs[kk][tx * 4]);
#pragma unroll
            for (int r = 0; r < 8; r++)
#pragma unroll
                for (int c = 0; c < 4; c++) acc[r][c] += a[r] * bv[c];
        }
        __syncthreads();
    }
#pragma unroll
    for (int r = 0; r < 8; r++) {
        int m = m0 + ty * 8 + r;
#pragma unroll
        for (int c = 0; c < 4; c++) {
            int n = n0 + tx * 4 + c;
            g_xg0[(size_t)m * G4 + n] = acc[r][c] + b_ih[n] + b_hh[n];
        }
    }
}

// ---------------------------------------------------------------------------
// Shared K=1024 GEMM accumulation: block covers M=128 (all b) x N=32 local
// cols (8 units x 4 gates, c_local = g*8 + jj -> W row g*H + j0 + jj).
// 256 threads, 8x2 accum per thread (ty: 8 rows, tx: 2 cols).
// ---------------------------------------------------------------------------
__device__ __forceinline__ void gemm_k1024(const float* __restrict__ Aglob,
                                           const float* __restrict__ Wglob,
                                           int j0, int tid, int ty, int tx,
                                           float (&acc)[8][2],
                                           float (*As)[132], float (*Bs)[36]) {
    for (int k0 = 0; k0 < Hn; k0 += 16) {
        // Load A tile (h): 128 rows x 16 k
#pragma unroll
        for (int i = 0; i < 2; i++) {
            int idx = tid + i * 256;
            int row = idx >> 2;
            int kq  = idx & 3;
            float4 v = *reinterpret_cast<const float4*>(
                Aglob + (size_t)row * Hn + k0 + kq * 4);
            As[kq * 4 + 0][row] = v.x;
            As[kq * 4 + 1][row] = v.y;
            As[kq * 4 + 2][row] = v.z;
            As[kq * 4 + 3][row] = v.w;
        }
        // Load W tile: 32 rows x 16 k (128 float4)
        if (tid < 128) {
            int row = tid >> 2;          // c_local 0..31
            int kq  = tid & 3;
            int g = row >> 3, jj = row & 7;
            float4 v = *reinterpret_cast<const float4*>(
                Wglob + (size_t)(g * Hn + j0 + jj) * Hn + k0 + kq * 4);
            Bs[kq * 4 + 0][row] = v.x;
            Bs[kq * 4 + 1][row] = v.y;
            Bs[kq * 4 + 2][row] = v.z;
            Bs[kq * 4 + 3][row] = v.w;
        }
        __syncthreads();
#pragma unroll
        for (int kk = 0; kk < 16; kk++) {
            float a[8];
            *reinterpret_cast<float4*>(&a[0]) =
                *reinterpret_cast<const float4*>(&As[kk][ty * 8]);
            *reinterpret_cast<float4*>(&a[4]) =
                *reinterpret_cast<const float4*>(&As[kk][ty * 8 + 4]);
            float b0 = Bs[kk][tx * 2];
            float b1 = Bs[kk][tx * 2 + 1];
#pragma unroll
            for (int r = 0; r < 8; r++) {
                acc[r][0] += a[r] * b0;
                acc[r][1] += a[r] * b1;
            }
        }
        __syncthreads();
    }
}

__device__ __forceinline__ float sigmoidf_(float x) {
    return 1.f / (1.f + expf(-x));
}

// ---------------------------------------------------------------------------
// Layer-0 step: gates = xg0[t] + h0 @ W_hh0^T ; cell update -> h0, c0
// ---------------------------------------------------------------------------
__global__ void lstm_step0(const float* __restrict__ Whh, int t) {
    __shared__ float As[16][132];
    __shared__ float Bs[16][36];
    __shared__ float Sg[128][33];
    const int tid = threadIdx.x;
    const int ty = tid >> 4, tx = tid & 15;
    const int j0 = blockIdx.x * 8;
    const float* h_in  = g_h0[t & 1];
    float*       h_out = g_h0[(t + 1) & 1];

    float acc[8][2] = {};
    gemm_k1024(h_in, Whh, j0, tid, ty, tx, acc, As, Bs);

#pragma unroll
    for (int r = 0; r < 8; r++) {
        Sg[ty * 8 + r][tx * 2]     = acc[r][0];
        Sg[ty * 8 + r][tx * 2 + 1] = acc[r][1];
    }
    __syncthreads();

    const size_t tbase = (size_t)t * Bn * G4;
#pragma unroll
    for (int i = 0; i < 4; i++) {
        int p = tid + i * 256;          // 0..1023
        int b = p >> 3, jj = p & 7;
        int j = j0 + jj;
        const float* xg = g_xg0 + tbase + (size_t)b * G4 + j;
        float pi = Sg[b][jj]      + xg[0];
        float pf = Sg[b][8 + jj]  + xg[Hn];
        float pg = Sg[b][16 + jj] + xg[2 * Hn];
        float po = Sg[b][24 + jj] + xg[3 * Hn];
        float ii = sigmoidf_(pi);
        float ff = sigmoidf_(pf);
        float gv = tanhf(pg);
        float oo = sigmoidf_(po);
        float c = ff * g_c0[b * Hn + j] + ii * gv;
        g_c0[b * Hn + j]  = c;
        h_out[b * Hn + j] = oo * tanhf(c);
    }
}

// ---------------------------------------------------------------------------
// Layer-1 step: gates = h0_new @ W_ih1^T + h1 @ W_hh1^T + b ; cell -> h1, c1
// ---------------------------------------------------------------------------
__global__ void lstm_step1(const float* __restrict__ Wih,
                           const float* __restrict__ Whh,
                           const float* __restrict__ b_ih,
                           const float* __restrict__ b_hh, int t) {
    __shared__ float As[16][132];
    __shared__ float Bs[16][36];
    __shared__ float Sg[128][33];
    const int tid = threadIdx.x;
    const int ty = tid >> 4, tx = tid & 15;
    const int j0 = blockIdx.x * 8;
    const float* h0_new = g_h0[(t + 1) & 1];   // layer-0 output of this step
    const float* h1_in  = g_h1[t & 1];
    float*       h1_out = g_h1[(t + 1) & 1];

    float acc[8][2] = {};
    gemm_k1024(h0_new, Wih, j0, tid, ty, tx, acc, As, Bs);
    gemm_k1024(h1_in,  Whh, j0, tid, ty, tx, acc, As, Bs);

#pragma unroll
    for (int r = 0; r < 8; r++) {
        Sg[ty * 8 + r][tx * 2]     = acc[r][0];
        Sg[ty * 8 + r][tx * 2 + 1] = acc[r][1];
    }
    __syncthreads();

#pragma unroll
    for (int i = 0; i < 4; i++) {
        int p = tid + i * 256;
        int b = p >> 3, jj = p & 7;
        int j = j0 + jj;
        float pi = Sg[b][jj]      + b_ih[j]          + b_hh[j];
        float pf = Sg[b][8 + jj]  + b_ih[Hn + j]     + b_hh[Hn + j];
        float pg = Sg[b][16 + jj] + b_ih[2 * Hn + j] + b_hh[2 * Hn + j];
        float po = Sg[b][24 + jj] + b_ih[3 * Hn + j] + b_hh[3 * Hn + j];
        float ii = sigmoidf_(pi);
        float ff = sigmoidf_(pf);
        float gv = tanhf(pg);
        float oo = sigmoidf_(po);
        float c = ff * g_c1[b * Hn + j] + ii * gv;
        g_c1[b * Hn + j]  = c;
        h1_out[b * Hn + j] = oo * tanhf(c);
    }
}

// ---------------------------------------------------------------------------
// Final head: out[b][r] = elu(h1_last[b] . W_br[r] + b_br[r])
// One block per batch row; thread r computes one output.
// ---------------------------------------------------------------------------
__global__ void br_kernel(const float* __restrict__ Wbr,
                          const float* __restrict__ bbr,
                          float* __restrict__ out) {
    __shared__ float hs[Hn];
    const int b = blockIdx.x;
    const float* h1 = g_h1[Tn & 1];   // T=256 even -> final h in buffer 0
    for (int k = threadIdx.x; k < Hn; k += 256) hs[k] = h1[b * Hn + k];
    __syncthreads();
    const int r = threadIdx.x;
    float acc = bbr[r];
    const float* w = Wbr + (size_t)r * Hn;
    for (int k = 0; k < Hn; k += 4) {
        float4 wv = *reinterpret_cast<const float4*>(w + k);
        float4 hv = *reinterpret_cast<const float4*>(&hs[k]);
        acc += wv.x * hv.x + wv.y * hv.y + wv.z * hv.z + wv.w * hv.w;
    }
    out[b * BRn + r] = acc > 0.f ? acc : expm1f(acc);
}

// ---------------------------------------------------------------------------
extern "C" void kernel_launch(void* const* d_in, const int* in_sizes, int n_in,
                              void* d_out, int out_size) {
    const float* X     = (const float*)d_in[0];
    const float* W_ih0 = (const float*)d_in[1];
    const float* W_hh0 = (const float*)d_in[2];
    const float* b_ih0 = (const float*)d_in[3];
    const float* b_hh0 = (const float*)d_in[4];
    const float* W_ih1 = (const float*)d_in[5];
    const float* W_hh1 = (const float*)d_in[6];
    const float* b_ih1 = (const float*)d_in[7];
    const float* b_hh1 = (const float*)d_in[8];
    const float* W_br  = (const float*)d_in[9];
    const float* b_br  = (const float*)d_in[10];
    float* out = (float*)d_out;

    init_state_kernel<<<(Bn * Hn + 255) / 256, 256>>>();

    dim3 gp(G4 / 64, (Tn * Bn) / 128);   // (64, 256)
    xg0_kernel<<<gp, 256>>>(X, W_ih0, b_ih0, b_hh0);

    for (int t = 0; t < Tn; t++) {
        lstm_step0<<<Hn / 8, 256>>>(W_hh0, t);
        lstm_step1<<<Hn / 8, 256>>>(W_ih1, W_hh1, b_ih1, b_hh1, t);
    }

    br_kernel<<<Bn, 256>>>(W_br, b_br, out);
}

// round 3
// speedup vs baseline: 2.4314x; 2.4314x over previous
#include <cuda_runtime.h>
#include <cuda_bf16.h>
#include <math.h>
#include <stdint.h>

#define Bn   128
#define Tn   256
#define DIN  512
#define Hn   1024
#define G4   4096
#define BRn  256

#define NSTAGE 4
#define STAGEB 16384                 // 8KB A + 8KB W per stage
#define SMEM_BYTES (NSTAGE * STAGEB)

#define SWZ128(o) ((o) ^ (((o) >> 3) & 0x70))

// ---------------------------------------------------------------------------
// Device scratch
// ---------------------------------------------------------------------------
__device__ float          g_xg0p[(size_t)Tn * Bn * G4];      // [t][b][p], p = 4*j+g, biases folded
__device__ __nv_bfloat16  g_Xhi[(size_t)Bn * Tn * DIN];
__device__ __nv_bfloat16  g_Xlo[(size_t)Bn * Tn * DIN];
__device__ __nv_bfloat16  g_W0i_hi[(size_t)G4 * DIN],  g_W0i_lo[(size_t)G4 * DIN];
__device__ __nv_bfloat16  g_W0h_hi[(size_t)G4 * Hn],   g_W0h_lo[(size_t)G4 * Hn];
__device__ __nv_bfloat16  g_W1_hi[(size_t)G4 * 2 * Hn], g_W1_lo[(size_t)G4 * 2 * Hn];
__device__ float          g_b0p[G4], g_b1p[G4];
// Concat activation buffers: rows = batch(128), cols: [0,1024)=h0, [1024,2048)=h1
__device__ __nv_bfloat16  g_Ahi[2][(size_t)Bn * 2 * Hn];
__device__ __nv_bfloat16  g_Alo[2][(size_t)Bn * 2 * Hn];
__device__ float          g_c0[Bn * Hn], g_c1[Bn * Hn];

__device__ __forceinline__ void split2(float x, __nv_bfloat16& hi, __nv_bfloat16& lo) {
    hi = __float2bfloat16(x);
    lo = __float2bfloat16(x - __bfloat162float(hi));
}

// ---------------------------------------------------------------------------
// MMA primitives (portable sm_80+ path: ldmatrix + mma.sync bf16)
// ---------------------------------------------------------------------------
__device__ __forceinline__ uint32_t smem_u32(const void* p) {
    uint32_t a;
    asm("{ .reg .u64 t; cvta.to.shared.u64 t, %1; cvt.u32.u64 %0, t; }"
        : "=r"(a) : "l"(p));
    return a;
}
__device__ __forceinline__ void ldsm4(uint32_t* r, uint32_t addr) {
    asm volatile("ldmatrix.sync.aligned.m8n8.x4.shared.b16 {%0,%1,%2,%3}, [%4];"
                 : "=r"(r[0]), "=r"(r[1]), "=r"(r[2]), "=r"(r[3]) : "r"(addr));
}
__device__ __forceinline__ void hmma(float* d, const uint32_t* a, uint32_t b0, uint32_t b1) {
    asm volatile("mma.sync.aligned.m16n8k16.row.col.f32.bf16.bf16.f32 "
                 "{%0,%1,%2,%3}, {%4,%5,%6,%7}, {%8,%9}, {%0,%1,%2,%3};"
                 : "+f"(d[0]), "+f"(d[1]), "+f"(d[2]), "+f"(d[3])
                 : "r"(a[0]), "r"(a[1]), "r"(a[2]), "r"(a[3]), "r"(b0), "r"(b1));
}
__device__ __forceinline__ void cp16(uint32_t so, const void* g) {
    asm volatile("cp.async.cg.shared.global [%0], [%1], 16;" :: "r"(so), "l"(g));
}
#define CP_COMMIT() asm volatile("cp.async.commit_group;" ::: "memory")
#define CP_WAIT2()  asm volatile("cp.async.wait_group 2;"  ::: "memory")

// One K=64 chunk of MMAs: A 64x64 at sA, W 64x64 at sW (both SW128, 128B rows).
__device__ __forceinline__ void mma_chunk(uint32_t sA, uint32_t sW,
                                          int wm, int wn, int lane, float acc[4][4]) {
#pragma unroll
    for (int ks = 0; ks < 4; ks++) {
        uint32_t a[4];
        int arow = wm * 16 + (lane & 15);
        int akb  = (ks * 16 + (lane >> 4) * 8) * 2;   // bytes
        ldsm4(a, sA + SWZ128(arow * 128 + akb));
#pragma unroll
        for (int nb = 0; nb < 2; nb++) {
            uint32_t b[4];
            int brow = wn * 32 + nb * 16 + (lane & 15);
            ldsm4(b, sW + SWZ128(brow * 128 + akb));
            hmma(acc[nb * 2 + 0], a, b[0], b[2]);   // n-group 0 (cols +0..7)
            hmma(acc[nb * 2 + 1], a, b[1], b[3]);   // n-group 1 (cols +8..15)
        }
    }
}

// Write warp accumulators into Sg[64][68]
__device__ __forceinline__ void acc_to_smem(float (*Sg)[68], int wm, int wn, int lane,
                                            float acc[4][4]) {
#pragma unroll
    for (int nb = 0; nb < 2; nb++)
#pragma unroll
        for (int g = 0; g < 2; g++) {
            int f  = nb * 2 + g;
            int cc = wn * 32 + nb * 16 + g * 8 + (lane & 3) * 2;
            int rr = wm * 16 + (lane >> 2);
            Sg[rr][cc]     = acc[f][0];
            Sg[rr][cc + 1] = acc[f][1];
            Sg[rr + 8][cc]     = acc[f][2];
            Sg[rr + 8][cc + 1] = acc[f][3];
        }
}

// ---------------------------------------------------------------------------
// Prep kernels
// ---------------------------------------------------------------------------
__global__ void split_X_kernel(const float* __restrict__ X) {
    size_t i = (size_t)blockIdx.x * blockDim.x + threadIdx.x;
    if (i < (size_t)Bn * Tn * DIN) split2(X[i], g_Xhi[i], g_Xlo[i]);
}
__global__ void pack_w0i_kernel(const float* __restrict__ W) {
    size_t i = (size_t)blockIdx.x * blockDim.x + threadIdx.x;
    if (i >= (size_t)G4 * DIN) return;
    int p = (int)(i / DIN), k = (int)(i % DIN);
    int j = p >> 2, g = p & 3;
    split2(W[(size_t)(g * Hn + j) * DIN + k], g_W0i_hi[i], g_W0i_lo[i]);
}
__global__ void pack_w0h_kernel(const float* __restrict__ W) {
    size_t i = (size_t)blockIdx.x * blockDim.x + threadIdx.x;
    if (i >= (size_t)G4 * Hn) return;
    int p = (int)(i / Hn), k = (int)(i % Hn);
    int j = p >> 2, g = p & 3;
    split2(W[(size_t)(g * Hn + j) * Hn + k], g_W0h_hi[i], g_W0h_lo[i]);
}
__global__ void pack_w1_kernel(const float* __restrict__ Wih,
                               const float* __restrict__ Whh) {
    size_t i = (size_t)blockIdx.x * blockDim.x + threadIdx.x;
    if (i >= (size_t)G4 * 2 * Hn) return;
    int p = (int)(i / (2 * Hn)), k = (int)(i % (2 * Hn));
    int j = p >> 2, g = p & 3;
    float v = (k < Hn) ? Wih[(size_t)(g * Hn + j) * Hn + k]
                       : Whh[(size_t)(g * Hn + j) * Hn + (k - Hn)];
    split2(v, g_W1_hi[i], g_W1_lo[i]);
}
__global__ void pack_bias_kernel(const float* __restrict__ bi0, const float* __restrict__ bh0,
                                 const float* __restrict__ bi1, const float* __restrict__ bh1) {
    int p = blockIdx.x * blockDim.x + threadIdx.x;
    if (p >= G4) return;
    int j = p >> 2, g = p & 3;
    g_b0p[p] = bi0[g * Hn + j] + bh0[g * Hn + j];
    g_b1p[p] = bi1[g * Hn + j] + bh1[g * Hn + j];
}
__global__ void init_state_kernel() {
    int i = blockIdx.x * blockDim.x + threadIdx.x;
    __nv_bfloat16 z = __float2bfloat16(0.f);
    if (i < Bn * 2 * Hn) {
        g_Ahi[0][i] = z; g_Alo[0][i] = z;
        g_Ahi[1][i] = z; g_Alo[1][i] = z;
    }
    if (i < Bn * Hn) { g_c0[i] = 0.f; g_c1[i] = 0.f; }
}

// ---------------------------------------------------------------------------
// xg0 GEMM: xg0p[m][p] = X[m] . W0i[p] (3-pass) + b0p[p];  m = t*128+b
// grid (64 ntiles, 512 mtiles), 256 threads. K=512, NIT = 24.
// ---------------------------------------------------------------------------
__device__ __forceinline__ void load_stage_xg0(char* smem, int s, int it, int m0, int p0,
                                               int tid) {
    const int kchunks = DIN / 64;
    int p = it / kchunks, kc = it % kchunks;
    const __nv_bfloat16* As = (p == 2) ? g_Xlo : g_Xhi;
    const __nv_bfloat16* Ws = (p == 1) ? g_W0i_lo : g_W0i_hi;
    uint32_t sbase = smem_u32(smem) + s * STAGEB;
#pragma unroll
    for (int j = 0; j < 2; j++) {
        int idx = tid + j * 256;
        int r = idx >> 3, q = idx & 7;
        int m = m0 + r;
        int t = m >> 7, b = m & 127;
        cp16(sbase + SWZ128(r * 128 + q * 16),
             As + ((size_t)b * Tn + t) * DIN + kc * 64 + q * 8);
    }
#pragma unroll
    for (int j = 0; j < 2; j++) {
        int idx = tid + j * 256;
        int r = idx >> 3, q = idx & 7;
        cp16(sbase + 8192 + SWZ128(r * 128 + q * 16),
             Ws + (size_t)(p0 + r) * DIN + kc * 64 + q * 8);
    }
    CP_COMMIT();
}

__global__ __launch_bounds__(256) void xg0_hmma(void) {
    extern __shared__ char smem[];
    const int tid = threadIdx.x, lane = tid & 31, wid = tid >> 5;
    const int wm = wid & 3, wn = wid >> 2;
    const int p0 = blockIdx.x * 64, m0 = blockIdx.y * 64;
    const int NIT = 3 * (DIN / 64);

    float acc[4][4] = {};
    for (int s = 0; s < NSTAGE - 1; s++) load_stage_xg0(smem, s, s, m0, p0, tid);
    uint32_t sb0 = smem_u32(smem);
    for (int it = 0; it < NIT; it++) {
        int s = it & (NSTAGE - 1);
        CP_WAIT2();
        __syncthreads();
        mma_chunk(sb0 + s * STAGEB, sb0 + s * STAGEB + 8192, wm, wn, lane, acc);
        int n2 = it + NSTAGE - 1;
        if (n2 < NIT) load_stage_xg0(smem, n2 & (NSTAGE - 1), n2, m0, p0, tid);
    }
    __syncthreads();
    float (*Sg)[68] = (float(*)[68])smem;
    acc_to_smem(Sg, wm, wn, lane, acc);
    __syncthreads();
#pragma unroll
    for (int i = 0; i < 4; i++) {
        int idx = tid + i * 256;          // 1024 float4 stores
        int r = idx >> 4, c4 = (idx & 15) * 4;
        float4 v;
        v.x = Sg[r][c4 + 0] + g_b0p[p0 + c4 + 0];
        v.y = Sg[r][c4 + 1] + g_b0p[p0 + c4 + 1];
        v.z = Sg[r][c4 + 2] + g_b0p[p0 + c4 + 2];
        v.w = Sg[r][c4 + 3] + g_b0p[p0 + c4 + 3];
        *(float4*)(g_xg0p + (size_t)(m0 + r) * G4 + p0 + c4) = v;
    }
}

// ---------------------------------------------------------------------------
// LSTM step: gates[64x64 tile] = A[64xK] @ W^T (3-pass) (+xg | +bias); cell update.
// A rows have stride 2048 (concat buffer). grid (64 ntiles, 2 m-halves).
// ---------------------------------------------------------------------------
__device__ __forceinline__ void load_stage_step(char* smem, int s, int it, int kchunks,
                                                const __nv_bfloat16* Ahi,
                                                const __nv_bfloat16* Alo,
                                                const __nv_bfloat16* Whi,
                                                const __nv_bfloat16* Wlo,
                                                int Kw, int m0, int p0, int tid) {
    int p = it / kchunks, kc = it % kchunks;
    const __nv_bfloat16* As = (p == 2) ? Alo : Ahi;
    const __nv_bfloat16* Ws = (p == 1) ? Wlo : Whi;
    uint32_t sbase = smem_u32(smem) + s * STAGEB;
#pragma unroll
    for (int j = 0; j < 2; j++) {
        int idx = tid + j * 256;
        int r = idx >> 3, q = idx & 7;
        cp16(sbase + SWZ128(r * 128 + q * 16),
             As + (size_t)(m0 + r) * (2 * Hn) + kc * 64 + q * 8);
    }
#pragma unroll
    for (int j = 0; j < 2; j++) {
        int idx = tid + j * 256;
        int r = idx >> 3, q = idx & 7;
        cp16(sbase + 8192 + SWZ128(r * 128 + q * 16),
             Ws + (size_t)(p0 + r) * Kw + kc * 64 + q * 8);
    }
    CP_COMMIT();
}

__global__ __launch_bounds__(256) void lstm_step_hmma(
    const __nv_bfloat16* __restrict__ Ahi, const __nv_bfloat16* __restrict__ Alo,
    const __nv_bfloat16* __restrict__ Whi, const __nv_bfloat16* __restrict__ Wlo,
    int kchunks, int Kw,
    const float* __restrict__ xg,      // per-t packed [b][4096], or null
    const float* __restrict__ biasp,   // packed [4096], or null
    float* __restrict__ cbuf,          // [128*1024]
    __nv_bfloat16* __restrict__ hhi,   // out base (col pre-offset), row stride 2048
    __nv_bfloat16* __restrict__ hlo) {
    extern __shared__ char smem[];
    const int tid = threadIdx.x, lane = tid & 31, wid = tid >> 5;
    const int wm = wid & 3, wn = wid >> 2;
    const int ntile = blockIdx.x, mh = blockIdx.y;
    const int p0 = ntile * 64, m0 = mh * 64;
    const int NIT = 3 * kchunks;

    float acc[4][4] = {};
    for (int s = 0; s < NSTAGE - 1; s++)
        load_stage_step(smem, s, s, kchunks, Ahi, Alo, Whi, Wlo, Kw, m0, p0, tid);
    uint32_t sb0 = smem_u32(smem);
    for (int it = 0; it < NIT; it++) {
        int s = it & (NSTAGE - 1);
        CP_WAIT2();
        __syncthreads();
        mma_chunk(sb0 + s * STAGEB, sb0 + s * STAGEB + 8192, wm, wn, lane, acc);
        int n2 = it + NSTAGE - 1;
        if (n2 < NIT)
            load_stage_step(smem, n2 & (NSTAGE - 1), n2, kchunks,
                            Ahi, Alo, Whi, Wlo, Kw, m0, p0, tid);
    }
    __syncthreads();
    float (*Sg)[68] = (float(*)[68])smem;
    acc_to_smem(Sg, wm, wn, lane, acc);
    __syncthreads();

#pragma unroll
    for (int i = 0; i < 4; i++) {
        int linear = tid + i * 256;       // 64 rows x 16 units
        int m = linear >> 4, u = linear & 15;
        int b = m0 + m;
        float pi_, pf, pg, po;
        if (xg) {
            const float4 xv = *(const float4*)(xg + (size_t)b * G4 + p0 + u * 4);
            pi_ = Sg[m][u * 4 + 0] + xv.x;
            pf  = Sg[m][u * 4 + 1] + xv.y;
            pg  = Sg[m][u * 4 + 2] + xv.z;
            po  = Sg[m][u * 4 + 3] + xv.w;
        } else {
            const float4 bv = *(const float4*)(biasp + p0 + u * 4);
            pi_ = Sg[m][u * 4 + 0] + bv.x;
            pf  = Sg[m][u * 4 + 1] + bv.y;
            pg  = Sg[m][u * 4 + 2] + bv.z;
            po  = Sg[m][u * 4 + 3] + bv.w;
        }
        int j  = ntile * 16 + u;
        int ci = b * Hn + j;
        float co = cbuf[ci];
        float ii = 1.f / (1.f + expf(-pi_));
        float ff = 1.f / (1.f + expf(-pf));
        float gg = tanhf(pg);
        float oo = 1.f / (1.f + expf(-po));
        float cn = ff * co + ii * gg;
        float h  = oo * tanhf(cn);
        cbuf[ci] = cn;
        size_t ho = (size_t)b * (2 * Hn) + j;
        __nv_bfloat16 hh = __float2bfloat16(h);
        hhi[ho] = hh;
        hlo[ho] = __float2bfloat16(h - __bfloat162float(hh));
    }
}

// ---------------------------------------------------------------------------
// Final head: out[b][r] = elu(h1_last[b] . W_br[r] + b_br[r]);  h1 = hi + lo
// ---------------------------------------------------------------------------
__global__ void br_kernel(const float* __restrict__ Wbr,
                          const float* __restrict__ bbr,
                          float* __restrict__ out) {
    __shared__ float hs[Hn];
    const int b = blockIdx.x;
    // final h1 written by layer1 at t=255 into parity (255&1)=1, cols [1024,2048)
    const __nv_bfloat16* hi = g_Ahi[1] + (size_t)b * (2 * Hn) + Hn;
    const __nv_bfloat16* lo = g_Alo[1] + (size_t)b * (2 * Hn) + Hn;
    for (int k = threadIdx.x; k < Hn; k += 256)
        hs[k] = __bfloat162float(hi[k]) + __bfloat162float(lo[k]);
    __syncthreads();
    const int r = threadIdx.x;
    float acc = bbr[r];
    const float* w = Wbr + (size_t)r * Hn;
    for (int k = 0; k < Hn; k += 4) {
        float4 wv = *reinterpret_cast<const float4*>(w + k);
        float4 hv = *reinterpret_cast<const float4*>(&hs[k]);
        acc += wv.x * hv.x + wv.y * hv.y + wv.z * hv.z + wv.w * hv.w;
    }
    out[b * BRn + r] = acc > 0.f ? acc : expm1f(acc);
}

// ---------------------------------------------------------------------------
extern "C" void kernel_launch(void* const* d_in, const int* in_sizes, int n_in,
                              void* d_out, int out_size) {
    const float* X     = (const float*)d_in[0];
    const float* W_ih0 = (const float*)d_in[1];
    const float* W_hh0 = (const float*)d_in[2];
    const float* b_ih0 = (const float*)d_in[3];
    const float* b_hh0 = (const float*)d_in[4];
    const float* W_ih1 = (const float*)d_in[5];
    const float* W_hh1 = (const float*)d_in[6];
    const float* b_ih1 = (const float*)d_in[7];
    const float* b_hh1 = (const float*)d_in[8];
    const float* W_br  = (const float*)d_in[9];
    const float* b_br  = (const float*)d_in[10];
    float* out = (float*)d_out;

    cudaFuncSetAttribute(xg0_hmma, cudaFuncAttributeMaxDynamicSharedMemorySize, SMEM_BYTES);
    cudaFuncSetAttribute(lstm_step_hmma, cudaFuncAttributeMaxDynamicSharedMemorySize, SMEM_BYTES);

    split_X_kernel<<<(Bn * Tn * DIN) / 256, 256>>>(X);
    pack_w0i_kernel<<<(G4 * DIN) / 256, 256>>>(W_ih0);
    pack_w0h_kernel<<<(G4 * Hn) / 256, 256>>>(W_hh0);
    pack_w1_kernel<<<(G4 * 2 * Hn) / 256, 256>>>(W_ih1, W_hh1);
    pack_bias_kernel<<<G4 / 256, 256>>>(b_ih0, b_hh0, b_ih1, b_hh1);
    init_state_kernel<<<(Bn * 2 * Hn) / 256, 256>>>();

    xg0_hmma<<<dim3(64, (Tn * Bn) / 64), 256, SMEM_BYTES>>>();

    __nv_bfloat16 *ahi, *alo, *w0hhi, *w0hlo, *w1hi, *w1lo;
    float *c0p, *c1p, *b1pp, *xg0p;
    cudaGetSymbolAddress((void**)&xg0p,  g_xg0p);
    cudaGetSymbolAddress((void**)&c0p,   g_c0);
    cudaGetSymbolAddress((void**)&c1p,   g_c1);
    cudaGetSymbolAddress((void**)&b1pp,  g_b1p);
    cudaGetSymbolAddress((void**)&w0hhi, g_W0h_hi);
    cudaGetSymbolAddress((void**)&w0hlo, g_W0h_lo);
    cudaGetSymbolAddress((void**)&w1hi,  g_W1_hi);
    cudaGetSymbolAddress((void**)&w1lo,  g_W1_lo);
    cudaGetSymbolAddress((void**)&ahi,   g_Ahi);
    cudaGetSymbolAddress((void**)&alo,   g_Alo);
    const size_t PAR = (size_t)Bn * 2 * Hn;

    for (int t = 0; t < Tn; t++) {
        int pi = t & 1, po = (t + 1) & 1;
        // layer 0: gates = h0(t) @ W_hh0^T + xg0[t];  h0 in cols [0,1024) of parity pi
        lstm_step_hmma<<<dim3(64, 2), 256, SMEM_BYTES>>>(
            ahi + pi * PAR, alo + pi * PAR, w0hhi, w0hlo, 16, Hn,
            xg0p + (size_t)t * Bn * G4, nullptr,
            c0p, ahi + po * PAR, alo + po * PAR);
        // layer 1: gates = [h0(t+1); h1(t)] @ W1^T + b1; A = full parity-po rows;
        //          writes h1(t+1) into parity pi, cols [1024,2048)
        lstm_step_hmma<<<dim3(64, 2), 256, SMEM_BYTES>>>(
            ahi + po * PAR, alo + po * PAR, w1hi, w1lo, 32, 2 * Hn,
            nullptr, b1pp,
            c1p, ahi + pi * PAR + Hn, alo + pi * PAR + Hn);
    }

    br_kernel<<<Bn, 256>>>(W_br, b_br, out);
}

// round 5
// speedup vs baseline: 4.1699x; 1.7150x over previous
#include <cuda_runtime.h>
#include <cuda_bf16.h>
#include <math.h>
#include <stdint.h>

#define Bn   128
#define Tn   256
#define DIN  512
#define Hn   1024
#define G4   4096
#define BRn  256

#define K0   1536            // layer0 concat K: [h0(1024) | x(512)]
#define K1   2048            // layer1 concat K: [h0(1024) | h1(1024)]
#define NCH0 24
#define NCH1 32

#define NSTAGE 3
#define ST_AHI 0
#define ST_ALO 8192
#define ST_WHI 16384
#define ST_WLO 24576
#define STAGEB 32768
#define SMEM_STAGES (NSTAGE * STAGEB)          // 98304
#define SMEM_BYTES  (SMEM_STAGES + 8192)       // + c-state [2][64][16] f32
#define NCTA 128

#define SWZ128(o) ((o) ^ (((o) >> 3) & 0x70))

// ---------------------------------------------------------------------------
// Device scratch
// ---------------------------------------------------------------------------
__device__ __nv_bfloat16 g_Xhi[(size_t)Bn * Tn * DIN];
__device__ __nv_bfloat16 g_Xlo[(size_t)Bn * Tn * DIN];
__device__ __nv_bfloat16 g_W0hi[(size_t)G4 * K0], g_W0lo[(size_t)G4 * K0];
__device__ __nv_bfloat16 g_W1hi[(size_t)G4 * K1], g_W1lo[(size_t)G4 * K1];
__device__ float         g_b0p[G4], g_b1p[G4];
__device__ __nv_bfloat16 g_h0hi[2][Bn * Hn], g_h0lo[2][Bn * Hn];
__device__ __nv_bfloat16 g_h1hi[2][Bn * Hn], g_h1lo[2][Bn * Hn];
__device__ unsigned int  g_bar;

__device__ __forceinline__ void split2(float x, __nv_bfloat16& hi, __nv_bfloat16& lo) {
    hi = __float2bfloat16(x);
    lo = __float2bfloat16(x - __bfloat162float(hi));
}

// ---------------------------------------------------------------------------
// MMA / async primitives (portable sm_80+ ISA: ldmatrix + mma.sync + cp.async)
// ---------------------------------------------------------------------------
__device__ __forceinline__ uint32_t smem_u32(const void* p) {
    uint32_t a;
    asm("{ .reg .u64 t; cvta.to.shared.u64 t, %1; cvt.u32.u64 %0, t; }"
        : "=r"(a) : "l"(p));
    return a;
}
__device__ __forceinline__ void ldsm4(uint32_t* r, uint32_t addr) {
    asm volatile("ldmatrix.sync.aligned.m8n8.x4.shared.b16 {%0,%1,%2,%3}, [%4];"
                 : "=r"(r[0]), "=r"(r[1]), "=r"(r[2]), "=r"(r[3]) : "r"(addr));
}
__device__ __forceinline__ void hmma(float* d, const uint32_t* a, uint32_t b0, uint32_t b1) {
    asm volatile("mma.sync.aligned.m16n8k16.row.col.f32.bf16.bf16.f32 "
                 "{%0,%1,%2,%3}, {%4,%5,%6,%7}, {%8,%9}, {%0,%1,%2,%3};"
                 : "+f"(d[0]), "+f"(d[1]), "+f"(d[2]), "+f"(d[3])
                 : "r"(a[0]), "r"(a[1]), "r"(a[2]), "r"(a[3]), "r"(b0), "r"(b1));
}
__device__ __forceinline__ void cp16(uint32_t so, const void* g) {
    asm volatile("cp.async.cg.shared.global [%0], [%1], 16;" :: "r"(so), "l"(g));
}
#define CP_COMMIT() asm volatile("cp.async.commit_group;" ::: "memory")
#define CP_WAIT1()  asm volatile("cp.async.wait_group 1;"  ::: "memory")
#define CP_WAIT0()  asm volatile("cp.async.wait_group 0;"  ::: "memory")

// Fused chunk load: A(hi,lo) 64x64 + W(hi,lo) 64x64, all SW128. 8 cp16/thread.
__device__ __forceinline__ void load_chunk(
    uint32_t sbase,
    const __nv_bfloat16* Ahi, const __nv_bfloat16* Alo, size_t Astride, int kcol,
    const __nv_bfloat16* Whi, const __nv_bfloat16* Wlo, size_t Wstride, int wkcol,
    int tid)
{
#pragma unroll
    for (int j = 0; j < 2; j++) {
        int idx = tid + j * 256;
        int r = idx >> 3, q = idx & 7;
        uint32_t sw = SWZ128(r * 128 + q * 16);
        cp16(sbase + ST_AHI + sw, Ahi + (size_t)r * Astride + kcol + q * 8);
        cp16(sbase + ST_ALO + sw, Alo + (size_t)r * Astride + kcol + q * 8);
        cp16(sbase + ST_WHI + sw, Whi + (size_t)r * Wstride + wkcol + q * 8);
        cp16(sbase + ST_WLO + sw, Wlo + (size_t)r * Wstride + wkcol + q * 8);
    }
    CP_COMMIT();
}

// One K=64 chunk: 3-pass MMAs (hi*hi + hi*lo + lo*hi). 24 LDSM + 48 HMMA / warp.
__device__ __forceinline__ void mma_chunk3(uint32_t st, int wm, int wn, int lane,
                                           float acc[4][4]) {
#pragma unroll
    for (int ks = 0; ks < 4; ks++) {
        int arow = wm * 16 + (lane & 15);
        int akb  = (ks * 16 + (lane >> 4) * 8) * 2;
        uint32_t ahi[4], alo[4];
        ldsm4(ahi, st + ST_AHI + SWZ128(arow * 128 + akb));
        ldsm4(alo, st + ST_ALO + SWZ128(arow * 128 + akb));
#pragma unroll
        for (int nb = 0; nb < 2; nb++) {
            int brow = wn * 32 + nb * 16 + (lane & 15);
            uint32_t bhi[4], blo[4];
            ldsm4(bhi, st + ST_WHI + SWZ128(brow * 128 + akb));
            ldsm4(blo, st + ST_WLO + SWZ128(brow * 128 + akb));
            hmma(acc[nb * 2 + 0], ahi, bhi[0], bhi[2]);
            hmma(acc[nb * 2 + 1], ahi, bhi[1], bhi[3]);
            hmma(acc[nb * 2 + 0], ahi, blo[0], blo[2]);
            hmma(acc[nb * 2 + 1], ahi, blo[1], blo[3]);
            hmma(acc[nb * 2 + 0], alo, bhi[0], bhi[2]);
            hmma(acc[nb * 2 + 1], alo, bhi[1], bhi[3]);
        }
    }
}

// Full pipelined 3-pass GEMM over nch chunks; A source switches at chunk 16.
// Tail-exact cp.async waits: the chunk consumed at iteration c must be complete
// (wait_group 0 on the final chunk, where only one group remains in flight).
__device__ __forceinline__ void gemm3(
    const __nv_bfloat16* A0h, const __nv_bfloat16* A0l, size_t s0,
    const __nv_bfloat16* A1h, const __nv_bfloat16* A1l, size_t s1,
    const __nv_bfloat16* Wh,  const __nv_bfloat16* Wl,  size_t Kw,
    int nch, int tid, int wm, int wn, int lane, uint32_t sb, float acc[4][4])
{
#pragma unroll
    for (int r = 0; r < 4; r++)
#pragma unroll
        for (int c = 0; c < 4; c++) acc[r][c] = 0.f;

    // prologue: chunks 0,1
#pragma unroll
    for (int c = 0; c < NSTAGE - 1; c++) {
        const __nv_bfloat16 *ah, *al; size_t st; int kc;
        if (c < 16) { ah = A0h; al = A0l; st = s0; kc = c * 64; }
        else        { ah = A1h; al = A1l; st = s1; kc = (c - 16) * 64; }
        load_chunk(sb + (c % NSTAGE) * STAGEB, ah, al, st, kc, Wh, Wl, Kw, c * 64, tid);
    }
    for (int c = 0; c < nch; c++) {
        if (c == nch - 1) { CP_WAIT0(); } else { CP_WAIT1(); }
        __syncthreads();
        mma_chunk3(sb + (c % NSTAGE) * STAGEB, wm, wn, lane, acc);
        int n2 = c + NSTAGE - 1;
        if (n2 < nch) {
            const __nv_bfloat16 *ah, *al; size_t st; int kc;
            if (n2 < 16) { ah = A0h; al = A0l; st = s0; kc = n2 * 64; }
            else         { ah = A1h; al = A1l; st = s1; kc = (n2 - 16) * 64; }
            load_chunk(sb + (n2 % NSTAGE) * STAGEB, ah, al, st, kc, Wh, Wl, Kw, n2 * 64, tid);
        }
    }
    __syncthreads();   // all warps done reading stages before Sg overlay
}

// acc -> Sg (stage0 smem overlay), then cell update + h write.
__device__ __forceinline__ void epilogue_cell(
    char* smem, float acc[4][4], int wm, int wn, int lane, int tid,
    const float* __restrict__ biasp, float* cseg,
    __nv_bfloat16* __restrict__ hhi, __nv_bfloat16* __restrict__ hlo,
    int m0, int p0)
{
    float (*Sg)[68] = (float(*)[68])smem;
#pragma unroll
    for (int nb = 0; nb < 2; nb++)
#pragma unroll
        for (int g = 0; g < 2; g++) {
            int f  = nb * 2 + g;
            int cc = wn * 32 + nb * 16 + g * 8 + (lane & 3) * 2;
            int rr = wm * 16 + (lane >> 2);
            Sg[rr][cc]     = acc[f][0];
            Sg[rr][cc + 1] = acc[f][1];
            Sg[rr + 8][cc]     = acc[f][2];
            Sg[rr + 8][cc + 1] = acc[f][3];
        }
    __syncthreads();
#pragma unroll
    for (int i = 0; i < 4; i++) {
        int lin = tid + i * 256;
        int m = lin >> 4, u = lin & 15;
        int b = m0 + m;
        int col = u * 4;
        float pi_ = Sg[m][col]     + biasp[p0 + col];
        float pf  = Sg[m][col + 1] + biasp[p0 + col + 1];
        float pg  = Sg[m][col + 2] + biasp[p0 + col + 2];
        float po  = Sg[m][col + 3] + biasp[p0 + col + 3];
        int ci = m * 16 + u;
        float co = cseg[ci];
        float ii = 1.f / (1.f + expf(-pi_));
        float ff = 1.f / (1.f + expf(-pf));
        float gg = tanhf(pg);
        float oo = 1.f / (1.f + expf(-po));
        float cn = ff * co + ii * gg;
        float h  = oo * tanhf(cn);
        cseg[ci] = cn;
        int j = (p0 >> 2) + u;
        __nv_bfloat16 hh = __float2bfloat16(h);
        hhi[(size_t)b * Hn + j] = hh;
        hlo[(size_t)b * Hn + j] = __float2bfloat16(h - __bfloat162float(hh));
    }
    __syncthreads();
}

// Grid-wide barrier (all NCTA CTAs co-resident; monotone counter, reset per launch)
__device__ __forceinline__ void grid_bar(unsigned target) {
    __syncthreads();
    if (threadIdx.x == 0) {
        __threadfence();
        atomicAdd(&g_bar, 1u);
        while (*(volatile unsigned int*)&g_bar < target) { __nanosleep(32); }
        __threadfence();
    }
    __syncthreads();
}

// ---------------------------------------------------------------------------
// Prep kernels
// ---------------------------------------------------------------------------
__global__ void split_X_kernel(const float* __restrict__ X) {
    size_t i = (size_t)blockIdx.x * blockDim.x + threadIdx.x;
    if (i < (size_t)Bn * Tn * DIN) split2(X[i], g_Xhi[i], g_Xlo[i]);
}
// W0 packed: row p = 4j+g, cols [0,1024)=W_hh0, [1024,1536)=W_ih0
__global__ void pack_w0_kernel(const float* __restrict__ Wih,
                               const float* __restrict__ Whh) {
    size_t i = (size_t)blockIdx.x * blockDim.x + threadIdx.x;
    if (i >= (size_t)G4 * K0) return;
    int p = (int)(i / K0), k = (int)(i % K0);
    int j = p >> 2, g = p & 3;
    float v = (k < Hn) ? Whh[(size_t)(g * Hn + j) * Hn + k]
                       : Wih[(size_t)(g * Hn + j) * DIN + (k - Hn)];
    split2(v, g_W0hi[i], g_W0lo[i]);
}
// W1 packed: cols [0,1024)=W_ih1 (input = h0), [1024,2048)=W_hh1
__global__ void pack_w1_kernel(const float* __restrict__ Wih,
                               const float* __restrict__ Whh) {
    size_t i = (size_t)blockIdx.x * blockDim.x + threadIdx.x;
    if (i >= (size_t)G4 * K1) return;
    int p = (int)(i / K1), k = (int)(i % K1);
    int j = p >> 2, g = p & 3;
    float v = (k < Hn) ? Wih[(size_t)(g * Hn + j) * Hn + k]
                       : Whh[(size_t)(g * Hn + j) * Hn + (k - Hn)];
    split2(v, g_W1hi[i], g_W1lo[i]);
}
__global__ void pack_bias_kernel(const float* __restrict__ bi0, const float* __restrict__ bh0,
                                 const float* __restrict__ bi1, const float* __restrict__ bh1) {
    int p = blockIdx.x * blockDim.x + threadIdx.x;
    if (p >= G4) return;
    int j = p >> 2, g = p & 3;
    g_b0p[p] = bi0[g * Hn + j] + bh0[g * Hn + j];
    g_b1p[p] = bi1[g * Hn + j] + bh1[g * Hn + j];
}
__global__ void init_state_kernel() {
    int i = blockIdx.x * blockDim.x + threadIdx.x;
    __nv_bfloat16 z = __float2bfloat16(0.f);
    if (i < Bn * Hn) {
        g_h0hi[0][i] = z; g_h0lo[0][i] = z; g_h0hi[1][i] = z; g_h0lo[1][i] = z;
        g_h1hi[0][i] = z; g_h1lo[0][i] = z; g_h1hi[1][i] = z; g_h1lo[1][i] = z;
    }
    if (i == 0) g_bar = 0u;
}

// ---------------------------------------------------------------------------
// Persistent LSTM kernel: 128 CTAs, one grid barrier per timestep.
// CTA (ntile, mh) owns gate cols [ntile*64, +64) and batch rows [mh*64, +64).
// phase t (0..254): layer1(t) then layer0(t+1), one barrier.
// ---------------------------------------------------------------------------
__global__ __launch_bounds__(256, 1) void lstm_persistent() {
    extern __shared__ char smem[];
    uint32_t sb = smem_u32(smem);
    float* cs0 = (float*)(smem + SMEM_STAGES);
    float* cs1 = cs0 + 1024;
    const int tid = threadIdx.x, lane = tid & 31, wid = tid >> 5;
    const int wm = wid & 3, wn = wid >> 2;
    const int ntile = blockIdx.x >> 1, mh = blockIdx.x & 1;
    const int p0 = ntile * 64, m0 = mh * 64;
    for (int i = tid; i < 2048; i += 256) cs0[i] = 0.f;
    __syncthreads();

    const size_t XS = (size_t)Tn * DIN;
    const __nv_bfloat16* W0h = g_W0hi + (size_t)p0 * K0;
    const __nv_bfloat16* W0l = g_W0lo + (size_t)p0 * K0;
    const __nv_bfloat16* W1h = g_W1hi + (size_t)p0 * K1;
    const __nv_bfloat16* W1l = g_W1lo + (size_t)p0 * K1;
    const size_t mh0 = (size_t)m0 * Hn;
    const size_t mhX = (size_t)m0 * XS;

    unsigned bar = 0;
    float acc[4][4];

    // initial layer0(0): A=[h0buf[1](zeros); X(0)] -> h0buf[0]
    gemm3(g_h0hi[1] + mh0, g_h0lo[1] + mh0, Hn,
          g_Xhi + mhX, g_Xlo + mhX, XS,
          W0h, W0l, K0, NCH0, tid, wm, wn, lane, sb, acc);
    epilogue_cell(smem, acc, wm, wn, lane, tid, g_b0p, cs0,
                  g_h0hi[0], g_h0lo[0], m0, p0);
    grid_bar(++bar * NCTA);

    for (int t = 0; t < Tn - 1; t++) {
        const int pc = t & 1, pn = (t + 1) & 1;
        // layer1(t): A=[h0buf[pc]; h1buf[pn]] -> h1buf[pc]
        gemm3(g_h0hi[pc] + mh0, g_h0lo[pc] + mh0, Hn,
              g_h1hi[pn] + mh0, g_h1lo[pn] + mh0, Hn,
              W1h, W1l, K1, NCH1, tid, wm, wn, lane, sb, acc);
        epilogue_cell(smem, acc, wm, wn, lane, tid, g_b1p, cs1,
                      g_h1hi[pc], g_h1lo[pc], m0, p0);
        // layer0(t+1): A=[h0buf[pc]; X(t+1)] -> h0buf[pn]
        gemm3(g_h0hi[pc] + mh0, g_h0lo[pc] + mh0, Hn,
              g_Xhi + (size_t)(t + 1) * DIN + mhX, g_Xlo + (size_t)(t + 1) * DIN + mhX, XS,
              W0h, W0l, K0, NCH0, tid, wm, wn, lane, sb, acc);
        epilogue_cell(smem, acc, wm, wn, lane, tid, g_b0p, cs0,
                      g_h0hi[pn], g_h0lo[pn], m0, p0);
        grid_bar(++bar * NCTA);
    }

    // final layer1(255): A=[h0buf[1]; h1buf[0]] -> h1buf[1]
    gemm3(g_h0hi[1] + mh0, g_h0lo[1] + mh0, Hn,
          g_h1hi[0] + mh0, g_h1lo[0] + mh0, Hn,
          W1h, W1l, K1, NCH1, tid, wm, wn, lane, sb, acc);
    epilogue_cell(smem, acc, wm, wn, lane, tid, g_b1p, cs1,
                  g_h1hi[1], g_h1lo[1], m0, p0);
}

// ---------------------------------------------------------------------------
// Final head: out[b][r] = elu(h1(255)[b] . W_br[r] + b_br[r]); h1 = hi + lo
// ---------------------------------------------------------------------------
__global__ void br_kernel(const float* __restrict__ Wbr,
                          const float* __restrict__ bbr,
                          float* __restrict__ out) {
    __shared__ float hs[Hn];
    const int b = blockIdx.x;
    const __nv_bfloat16* hi = g_h1hi[1] + (size_t)b * Hn;
    const __nv_bfloat16* lo = g_h1lo[1] + (size_t)b * Hn;
    for (int k = threadIdx.x; k < Hn; k += 256)
        hs[k] = __bfloat162float(hi[k]) + __bfloat162float(lo[k]);
    __syncthreads();
    const int r = threadIdx.x;
    float acc = bbr[r];
    const float* w = Wbr + (size_t)r * Hn;
    for (int k = 0; k < Hn; k += 4) {
        float4 wv = *reinterpret_cast<const float4*>(w + k);
        float4 hv = *reinterpret_cast<const float4*>(&hs[k]);
        acc += wv.x * hv.x + wv.y * hv.y + wv.z * hv.z + wv.w * hv.w;
    }
    out[b * BRn + r] = acc > 0.f ? acc : expm1f(acc);
}

// ---------------------------------------------------------------------------
extern "C" void kernel_launch(void* const* d_in, const int* in_sizes, int n_in,
                              void* d_out, int out_size) {
    const float* X     = (const float*)d_in[0];
    const float* W_ih0 = (const float*)d_in[1];
    const float* W_hh0 = (const float*)d_in[2];
    const float* b_ih0 = (const float*)d_in[3];
    const float* b_hh0 = (const float*)d_in[4];
    const float* W_ih1 = (const float*)d_in[5];
    const float* W_hh1 = (const float*)d_in[6];
    const float* b_ih1 = (const float*)d_in[7];
    const float* b_hh1 = (const float*)d_in[8];
    const float* W_br  = (const float*)d_in[9];
    const float* b_br  = (const float*)d_in[10];
    float* out = (float*)d_out;

    cudaFuncSetAttribute(lstm_persistent, cudaFuncAttributeMaxDynamicSharedMemorySize,
                         SMEM_BYTES);

    split_X_kernel<<<(Bn * Tn * DIN) / 256, 256>>>(X);
    pack_w0_kernel<<<((int)((size_t)G4 * K0 / 256)), 256>>>(W_ih0, W_hh0);
    pack_w1_kernel<<<((int)((size_t)G4 * K1 / 256)), 256>>>(W_ih1, W_hh1);
    pack_bias_kernel<<<G4 / 256, 256>>>(b_ih0, b_hh0, b_ih1, b_hh1);
    init_state_kernel<<<(Bn * Hn) / 256, 256>>>();

    lstm_persistent<<<NCTA, 256, SMEM_BYTES>>>();

    br_kernel<<<Bn, 256>>>(W_br, b_br, out);
}

// round 6
// speedup vs baseline: 4.6312x; 1.1106x over previous
#include <cuda_runtime.h>
#include <cuda_fp16.h>
#include <math.h>
#include <stdint.h>

#define Bn   128
#define Tn   256
#define DIN  512
#define Hn   1024
#define G4   4096
#define BRn  256

#define K0   1536            // layer0 concat K: [h0(1024) | x(512)]
#define K1   2048            // layer1 concat K: [h0(1024) | h1(1024)]
#define NCH0 24
#define NCH1 32

#define NSTAGE 4
#define ST_AHI 0
#define ST_ALO 8192
#define ST_W   16384
#define STAGEB 24576
#define SMEM_STAGES (NSTAGE * STAGEB)        // 98304
#define SMEM_SG  SMEM_STAGES                 // float Sg[64][68] = 17408
#define SMEM_CS  (SMEM_SG + 17408)           // c-state 2*64*16 f32 = 8192
#define SMEM_BYTES (SMEM_CS + 8192)          // 123904
#define NCTA 128

#define SWZ128(o) ((o) ^ (((o) >> 3) & 0x70))

// ---------------------------------------------------------------------------
// Device scratch
// ---------------------------------------------------------------------------
__device__ __half g_Xhi[(size_t)Bn * Tn * DIN];
__device__ __half g_Xlo[(size_t)Bn * Tn * DIN];
__device__ __half g_W0[(size_t)G4 * K0];     // packed, single fp16
__device__ __half g_W1[(size_t)G4 * K1];
__device__ float  g_b0p[G4], g_b1p[G4];
__device__ __half g_h0hi[2][Bn * Hn], g_h0lo[2][Bn * Hn];
__device__ __half g_h1hi[2][Bn * Hn], g_h1lo[2][Bn * Hn];
__device__ unsigned int g_bar;

__device__ __forceinline__ void split2h(float x, __half& hi, __half& lo) {
    hi = __float2half(x);
    lo = __float2half(x - __half2float(hi));
}

// ---------------------------------------------------------------------------
// MMA / async primitives (portable sm_80+ ISA)
// ---------------------------------------------------------------------------
__device__ __forceinline__ uint32_t smem_u32(const void* p) {
    uint32_t a;
    asm("{ .reg .u64 t; cvta.to.shared.u64 t, %1; cvt.u32.u64 %0, t; }"
        : "=r"(a) : "l"(p));
    return a;
}
__device__ __forceinline__ void ldsm4(uint32_t* r, uint32_t addr) {
    asm volatile("ldmatrix.sync.aligned.m8n8.x4.shared.b16 {%0,%1,%2,%3}, [%4];"
                 : "=r"(r[0]), "=r"(r[1]), "=r"(r[2]), "=r"(r[3]) : "r"(addr));
}
__device__ __forceinline__ void hmma16(float* d, const uint32_t* a, uint32_t b0, uint32_t b1) {
    asm volatile("mma.sync.aligned.m16n8k16.row.col.f32.f16.f16.f32 "
                 "{%0,%1,%2,%3}, {%4,%5,%6,%7}, {%8,%9}, {%0,%1,%2,%3};"
                 : "+f"(d[0]), "+f"(d[1]), "+f"(d[2]), "+f"(d[3])
                 : "r"(a[0]), "r"(a[1]), "r"(a[2]), "r"(a[3]), "r"(b0), "r"(b1));
}
__device__ __forceinline__ void cp16(uint32_t so, const void* g) {
    asm volatile("cp.async.cg.shared.global [%0], [%1], 16;" :: "r"(so), "l"(g));
}
#define CP_COMMIT() asm volatile("cp.async.commit_group;" ::: "memory")
#define CP_WAIT0()  asm volatile("cp.async.wait_group 0;"  ::: "memory")
#define CP_WAIT1()  asm volatile("cp.async.wait_group 1;"  ::: "memory")
#define CP_WAIT2()  asm volatile("cp.async.wait_group 2;"  ::: "memory")

// ---------------------------------------------------------------------------
// Job descriptor: one 64x64-output GEMM + cell update
// ---------------------------------------------------------------------------
struct Job {
    const __half *A0h, *A0l, *A1h, *A1l;   // A segments (switch at chunk 16)
    size_t s0, s1;                          // row strides (halves)
    const __half* W;                        // packed weights, row stride Kw
    size_t Kw;
    int nch;
    const float* biasp;
    float* cseg;                            // smem c-state [64*16]
    __half *hhi, *hlo;                      // global h out (index (m0+m)*Hn + j)
};

// Fused chunk load: A(hi,lo) 64x64 + W 64x64 fp16, SW128. 6 cp16/thread.
__device__ __forceinline__ void load_cc(const Job* jobs, int cc0, int cc,
                                        uint32_t sb, int tid) {
    const Job& J = jobs[cc >= cc0 ? 1 : 0];
    int lc = (cc >= cc0) ? cc - cc0 : cc;
    const __half *Ah, *Al; size_t As; int kc;
    if (lc < 16) { Ah = J.A0h; Al = J.A0l; As = J.s0; kc = lc * 64; }
    else         { Ah = J.A1h; Al = J.A1l; As = J.s1; kc = (lc - 16) * 64; }
    uint32_t sbase = sb + (cc % NSTAGE) * STAGEB;
    int wk = lc * 64;
#pragma unroll
    for (int j = 0; j < 2; j++) {
        int idx = tid + j * 256;
        int r = idx >> 3, q = idx & 7;
        uint32_t sw = SWZ128(r * 128 + q * 16);
        cp16(sbase + ST_AHI + sw, Ah + (size_t)r * As + kc + q * 8);
        cp16(sbase + ST_ALO + sw, Al + (size_t)r * As + kc + q * 8);
        cp16(sbase + ST_W   + sw, J.W + (size_t)r * J.Kw + wk + q * 8);
    }
    CP_COMMIT();
}

// One K=64 chunk, 2-pass (Ahi*W + Alo*W): 16 LDSM + 32 HMMA per warp.
__device__ __forceinline__ void mma_chunk2(uint32_t st, int wm, int wn, int lane,
                                           float acc[4][4]) {
#pragma unroll
    for (int ks = 0; ks < 4; ks++) {
        int arow = wm * 16 + (lane & 15);
        int akb  = (ks * 16 + (lane >> 4) * 8) * 2;
        uint32_t ahi[4], alo[4];
        ldsm4(ahi, st + ST_AHI + SWZ128(arow * 128 + akb));
        ldsm4(alo, st + ST_ALO + SWZ128(arow * 128 + akb));
#pragma unroll
        for (int nb = 0; nb < 2; nb++) {
            int brow = wn * 32 + nb * 16 + (lane & 15);
            uint32_t b[4];
            ldsm4(b, st + ST_W + SWZ128(brow * 128 + akb));
            hmma16(acc[nb * 2 + 0], ahi, b[0], b[2]);
            hmma16(acc[nb * 2 + 1], ahi, b[1], b[3]);
            hmma16(acc[nb * 2 + 0], alo, b[0], b[2]);
            hmma16(acc[nb * 2 + 1], alo, b[1], b[3]);
        }
    }
}

// acc -> Sg (dedicated buffer) -> gates -> cell update -> h hi/lo write.
__device__ __forceinline__ void epilogue_cell(
    char* smem, float acc[4][4], int wm, int wn, int lane, int tid,
    const Job& J, int m0, int p0)
{
    float (*Sg)[68] = (float(*)[68])(smem + SMEM_SG);
#pragma unroll
    for (int nb = 0; nb < 2; nb++)
#pragma unroll
        for (int g = 0; g < 2; g++) {
            int f  = nb * 2 + g;
            int cc = wn * 32 + nb * 16 + g * 8 + (lane & 3) * 2;
            int rr = wm * 16 + (lane >> 2);
            Sg[rr][cc]         = acc[f][0];
            Sg[rr][cc + 1]     = acc[f][1];
            Sg[rr + 8][cc]     = acc[f][2];
            Sg[rr + 8][cc + 1] = acc[f][3];
        }
    __syncthreads();
#pragma unroll
    for (int i = 0; i < 4; i++) {
        int lin = tid + i * 256;
        int m = lin >> 4, u = lin & 15;
        int b = m0 + m;
        int col = u * 4;
        float pi_ = Sg[m][col]     + J.biasp[p0 + col];
        float pf  = Sg[m][col + 1] + J.biasp[p0 + col + 1];
        float pg  = Sg[m][col + 2] + J.biasp[p0 + col + 2];
        float po  = Sg[m][col + 3] + J.biasp[p0 + col + 3];
        int ci = m * 16 + u;
        float co = J.cseg[ci];
        float ii = 1.f / (1.f + expf(-pi_));
        float ff = 1.f / (1.f + expf(-pf));
        float gg = tanhf(pg);
        float oo = 1.f / (1.f + expf(-po));
        float cn = ff * co + ii * gg;
        float h  = oo * tanhf(cn);
        J.cseg[ci] = cn;
        int j = (p0 >> 2) + u;
        __half hh = __float2half(h);
        J.hhi[(size_t)b * Hn + j] = hh;
        J.hlo[(size_t)b * Hn + j] = __float2half(h - __half2float(hh));
    }
}

// Run one phase: up to 2 jobs through a single continuous cp.async ring.
__device__ void phase_exec(const Job* jobs, int njobs, char* smem, uint32_t sb,
                           int tid, int wm, int wn, int lane, int m0, int p0) {
    const int cc0 = jobs[0].nch;
    const int TOT = cc0 + (njobs > 1 ? jobs[1].nch : 0);
    float acc[4][4];
#pragma unroll
    for (int r = 0; r < 4; r++)
#pragma unroll
        for (int c = 0; c < 4; c++) acc[r][c] = 0.f;

    int committed = 0;
    for (; committed < NSTAGE - 1; committed++)
        load_cc(jobs, cc0, committed, sb, tid);

    for (int c = 0; c < TOT; c++) {
        int pend = committed - c - 1;
        if (pend <= 0)      { CP_WAIT0(); }
        else if (pend == 1) { CP_WAIT1(); }
        else                { CP_WAIT2(); }
        __syncthreads();
        mma_chunk2(sb + (c % NSTAGE) * STAGEB, wm, wn, lane, acc);
        if (c == cc0 - 1) {
            epilogue_cell(smem, acc, wm, wn, lane, tid, jobs[0], m0, p0);
#pragma unroll
            for (int r = 0; r < 4; r++)
#pragma unroll
                for (int cl = 0; cl < 4; cl++) acc[r][cl] = 0.f;
        } else if (c == TOT - 1) {
            epilogue_cell(smem, acc, wm, wn, lane, tid, jobs[1], m0, p0);
        }
        if (committed < TOT) { load_cc(jobs, cc0, committed, sb, tid); committed++; }
    }
    __syncthreads();
}

// Grid-wide barrier (128 co-resident CTAs; monotone counter)
__device__ __forceinline__ void grid_bar(unsigned target) {
    __syncthreads();
    if (threadIdx.x == 0) {
        __threadfence();
        atomicAdd(&g_bar, 1u);
        while (*(volatile unsigned int*)&g_bar < target) { __nanosleep(32); }
        __threadfence();
    }
    __syncthreads();
}

// ---------------------------------------------------------------------------
// Prep kernels
// ---------------------------------------------------------------------------
__global__ void split_X_kernel(const float* __restrict__ X) {
    size_t i = (size_t)blockIdx.x * blockDim.x + threadIdx.x;
    if (i < (size_t)Bn * Tn * DIN) split2h(X[i], g_Xhi[i], g_Xlo[i]);
}
// W0 packed: row p = 4j+g, cols [0,1024)=W_hh0, [1024,1536)=W_ih0
__global__ void pack_w0_kernel(const float* __restrict__ Wih,
                               const float* __restrict__ Whh) {
    size_t i = (size_t)blockIdx.x * blockDim.x + threadIdx.x;
    if (i >= (size_t)G4 * K0) return;
    int p = (int)(i / K0), k = (int)(i % K0);
    int j = p >> 2, g = p & 3;
    float v = (k < Hn) ? Whh[(size_t)(g * Hn + j) * Hn + k]
                       : Wih[(size_t)(g * Hn + j) * DIN + (k - Hn)];
    g_W0[i] = __float2half(v);
}
// W1 packed: cols [0,1024)=W_ih1 (input = h0), [1024,2048)=W_hh1
__global__ void pack_w1_kernel(const float* __restrict__ Wih,
                               const float* __restrict__ Whh) {
    size_t i = (size_t)blockIdx.x * blockDim.x + threadIdx.x;
    if (i >= (size_t)G4 * K1) return;
    int p = (int)(i / K1), k = (int)(i % K1);
    int j = p >> 2, g = p & 3;
    float v = (k < Hn) ? Wih[(size_t)(g * Hn + j) * Hn + k]
                       : Whh[(size_t)(g * Hn + j) * Hn + (k - Hn)];
    g_W1[i] = __float2half(v);
}
__global__ void pack_bias_kernel(const float* __restrict__ bi0, const float* __restrict__ bh0,
                                 const float* __restrict__ bi1, const float* __restrict__ bh1) {
    int p = blockIdx.x * blockDim.x + threadIdx.x;
    if (p >= G4) return;
    int j = p >> 2, g = p & 3;
    g_b0p[p] = bi0[g * Hn + j] + bh0[g * Hn + j];
    g_b1p[p] = bi1[g * Hn + j] + bh1[g * Hn + j];
}
__global__ void init_state_kernel() {
    int i = blockIdx.x * blockDim.x + threadIdx.x;
    __half z = __float2half(0.f);
    if (i < Bn * Hn) {
        g_h0hi[0][i] = z; g_h0lo[0][i] = z; g_h0hi[1][i] = z; g_h0lo[1][i] = z;
        g_h1hi[0][i] = z; g_h1lo[0][i] = z; g_h1hi[1][i] = z; g_h1lo[1][i] = z;
    }
    if (i == 0) g_bar = 0u;
}

// ---------------------------------------------------------------------------
// Persistent LSTM: 128 CTAs; phase = {layer1(t), layer0(t+1)}; 1 barrier/phase.
// CTA (ntile, mh) owns gate cols [ntile*64,+64) and batch rows [mh*64,+64).
// ---------------------------------------------------------------------------
__global__ __launch_bounds__(256, 1) void lstm_persistent() {
    extern __shared__ char smem[];
    uint32_t sb = smem_u32(smem);
    const int tid = threadIdx.x, lane = tid & 31, wid = tid >> 5;
    const int wm = wid & 3, wn = wid >> 2;
    const int ntile = blockIdx.x >> 1, mh = blockIdx.x & 1;
    const int p0 = ntile * 64, m0 = mh * 64;
    float* cs0 = (float*)(smem + SMEM_CS);
    float* cs1 = cs0 + 1024;
    for (int i = tid; i < 2048; i += 256) cs0[i] = 0.f;
    __syncthreads();

    const size_t XS = (size_t)Tn * DIN;
    const __half* W0 = g_W0 + (size_t)p0 * K0;
    const __half* W1 = g_W1 + (size_t)p0 * K1;
    const size_t mh0 = (size_t)m0 * Hn;
    const size_t mhX = (size_t)m0 * XS;

    unsigned bar = 0;
    Job jb[2];

    // initial layer0(0): A=[h0[1](zeros); X(0)] -> h0[0]
    jb[0].A0h = g_h0hi[1] + mh0; jb[0].A0l = g_h0lo[1] + mh0;
    jb[0].A1h = g_Xhi + mhX;     jb[0].A1l = g_Xlo + mhX;
    jb[0].s0 = Hn; jb[0].s1 = XS;
    jb[0].W = W0; jb[0].Kw = K0; jb[0].nch = NCH0;
    jb[0].biasp = g_b0p; jb[0].cseg = cs0;
    jb[0].hhi = g_h0hi[0]; jb[0].hlo = g_h0lo[0];
    phase_exec(jb, 1, smem, sb, tid, wm, wn, lane, m0, p0);
    grid_bar(++bar * NCTA);

    for (int t = 0; t < Tn - 1; t++) {
        const int pc = t & 1, pn = (t + 1) & 1;
        // job0: layer1(t): A=[h0[pc]; h1[pn]] -> h1[pc]
        jb[0].A0h = g_h0hi[pc] + mh0; jb[0].A0l = g_h0lo[pc] + mh0;
        jb[0].A1h = g_h1hi[pn] + mh0; jb[0].A1l = g_h1lo[pn] + mh0;
        jb[0].s0 = Hn; jb[0].s1 = Hn;
        jb[0].W = W1; jb[0].Kw = K1; jb[0].nch = NCH1;
        jb[0].biasp = g_b1p; jb[0].cseg = cs1;
        jb[0].hhi = g_h1hi[pc]; jb[0].hlo = g_h1lo[pc];
        // job1: layer0(t+1): A=[h0[pc]; X(t+1)] -> h0[pn]
        jb[1].A0h = g_h0hi[pc] + mh0; jb[1].A0l = g_h0lo[pc] + mh0;
        jb[1].A1h = g_Xhi + (size_t)(t + 1) * DIN + mhX;
        jb[1].A1l = g_Xlo + (size_t)(t + 1) * DIN + mhX;
        jb[1].s0 = Hn; jb[1].s1 = XS;
        jb[1].W = W0; jb[1].Kw = K0; jb[1].nch = NCH0;
        jb[1].biasp = g_b0p; jb[1].cseg = cs0;
        jb[1].hhi = g_h0hi[pn]; jb[1].hlo = g_h0lo[pn];
        phase_exec(jb, 2, smem, sb, tid, wm, wn, lane, m0, p0);
        grid_bar(++bar * NCTA);
    }

    // final layer1(255): pc=1, pn=0 -> h1[1]
    jb[0].A0h = g_h0hi[1] + mh0; jb[0].A0l = g_h0lo[1] + mh0;
    jb[0].A1h = g_h1hi[0] + mh0; jb[0].A1l = g_h1lo[0] + mh0;
    jb[0].s0 = Hn; jb[0].s1 = Hn;
    jb[0].W = W1; jb[0].Kw = K1; jb[0].nch = NCH1;
    jb[0].biasp = g_b1p; jb[0].cseg = cs1;
    jb[0].hhi = g_h1hi[1]; jb[0].hlo = g_h1lo[1];
    phase_exec(jb, 1, smem, sb, tid, wm, wn, lane, m0, p0);
}

// ---------------------------------------------------------------------------
// Final head: out[b][r] = elu(h1(255)[b] . W_br[r] + b_br[r]); h1 = hi + lo
// ---------------------------------------------------------------------------
__global__ void br_kernel(const float* __restrict__ Wbr,
                          const float* __restrict__ bbr,
                          float* __restrict__ out) {
    __shared__ float hs[Hn];
    const int b = blockIdx.x;
    const __half* hi = g_h1hi[1] + (size_t)b * Hn;
    const __half* lo = g_h1lo[1] + (size_t)b * Hn;
    for (int k = threadIdx.x; k < Hn; k += 256)
        hs[k] = __half2float(hi[k]) + __half2float(lo[k]);
    __syncthreads();
    const int r = threadIdx.x;
    float acc = bbr[r];
    const float* w = Wbr + (size_t)r * Hn;
    for (int k = 0; k < Hn; k += 4) {
        float4 wv = *reinterpret_cast<const float4*>(w + k);
        float4 hv = *reinterpret_cast<const float4*>(&hs[k]);
        acc += wv.x * hv.x + wv.y * hv.y + wv.z * hv.z + wv.w * hv.w;
    }
    out[b * BRn + r] = acc > 0.f ? acc : expm1f(acc);
}

// ---------------------------------------------------------------------------
extern "C" void kernel_launch(void* const* d_in, const int* in_sizes, int n_in,
                              void* d_out, int out_size) {
    const float* X     = (const float*)d_in[0];
    const float* W_ih0 = (const float*)d_in[1];
    const float* W_hh0 = (const float*)d_in[2];
    const float* b_ih0 = (const float*)d_in[3];
    const float* b_hh0 = (const float*)d_in[4];
    const float* W_ih1 = (const float*)d_in[5];
    const float* W_hh1 = (const float*)d_in[6];
    const float* b_ih1 = (const float*)d_in[7];
    const float* b_hh1 = (const float*)d_in[8];
    const float* W_br  = (const float*)d_in[9];
    const float* b_br  = (const float*)d_in[10];
    float* out = (float*)d_out;

    cudaFuncSetAttribute(lstm_persistent, cudaFuncAttributeMaxDynamicSharedMemorySize,
                         SMEM_BYTES);

    split_X_kernel<<<(Bn * Tn * DIN) / 256, 256>>>(X);
    pack_w0_kernel<<<((int)((size_t)G4 * K0 / 256)), 256>>>(W_ih0, W_hh0);
    pack_w1_kernel<<<((int)((size_t)G4 * K1 / 256)), 256>>>(W_ih1, W_hh1);
    pack_bias_kernel<<<G4 / 256, 256>>>(b_ih0, b_hh0, b_ih1, b_hh1);
    init_state_kernel<<<(Bn * Hn) / 256, 256>>>();

    lstm_persistent<<<NCTA, 256, SMEM_BYTES>>>();

    br_kernel<<<Bn, 256>>>(W_br, b_br, out);
}

// round 7
// speedup vs baseline: 6.0121x; 1.2982x over previous
#include <cuda_runtime.h>
#include <cuda_fp16.h>
#include <math.h>
#include <stdint.h>

#define Bn   128
#define Tn   256
#define DIN  512
#define Hn   1024
#define G4   4096
#define BRn  256

#define K0   1536            // layer0 concat K: [h0(1024) | x(512)]
#define K1   2048            // layer1 concat K: [h0(1024) | h1(1024)]
#define NCH0 24
#define NCH1 32

#define NSTAGE 6
#define ST_A   0
#define ST_W   8192
#define STAGEB 16384
#define SMEM_STAGES (NSTAGE * STAGEB)        // 98304
#define SMEM_SG  SMEM_STAGES                 // float Sg[64][68] = 17408
#define SMEM_CS  (SMEM_SG + 17408)           // c-state 2*64*16 f32 = 8192
#define SMEM_BYTES (SMEM_CS + 8192)          // 123904
#define NCTA 128

#define SWZ128(o) ((o) ^ (((o) >> 3) & 0x70))

// ---------------------------------------------------------------------------
// Device scratch (all fp16 operands; c-state fp32 in smem)
// ---------------------------------------------------------------------------
__device__ __half g_X[(size_t)Bn * Tn * DIN];
__device__ __half g_W0[(size_t)G4 * K0];     // packed: row p=4j+g, [W_hh0 | W_ih0]
__device__ __half g_W1[(size_t)G4 * K1];     // packed: [W_ih1 | W_hh1]
__device__ float  g_b0p[G4], g_b1p[G4];
__device__ __half g_h0[2][Bn * Hn];
__device__ __half g_h1[2][Bn * Hn];
__device__ unsigned int g_bar;

// ---------------------------------------------------------------------------
// MMA / async primitives (portable sm_80+ ISA)
// ---------------------------------------------------------------------------
__device__ __forceinline__ uint32_t smem_u32(const void* p) {
    uint32_t a;
    asm("{ .reg .u64 t; cvta.to.shared.u64 t, %1; cvt.u32.u64 %0, t; }"
        : "=r"(a) : "l"(p));
    return a;
}
__device__ __forceinline__ void ldsm4(uint32_t* r, uint32_t addr) {
    asm volatile("ldmatrix.sync.aligned.m8n8.x4.shared.b16 {%0,%1,%2,%3}, [%4];"
                 : "=r"(r[0]), "=r"(r[1]), "=r"(r[2]), "=r"(r[3]) : "r"(addr));
}
__device__ __forceinline__ void hmma16(float* d, const uint32_t* a, uint32_t b0, uint32_t b1) {
    asm volatile("mma.sync.aligned.m16n8k16.row.col.f32.f16.f16.f32 "
                 "{%0,%1,%2,%3}, {%4,%5,%6,%7}, {%8,%9}, {%0,%1,%2,%3};"
                 : "+f"(d[0]), "+f"(d[1]), "+f"(d[2]), "+f"(d[3])
                 : "r"(a[0]), "r"(a[1]), "r"(a[2]), "r"(a[3]), "r"(b0), "r"(b1));
}
__device__ __forceinline__ void cp16(uint32_t so, const void* g) {
    asm volatile("cp.async.cg.shared.global [%0], [%1], 16;" :: "r"(so), "l"(g));
}
#define CP_COMMIT() asm volatile("cp.async.commit_group;" ::: "memory")
#define CP_WAIT0()  asm volatile("cp.async.wait_group 0;"  ::: "memory")
#define CP_WAIT1()  asm volatile("cp.async.wait_group 1;"  ::: "memory")
#define CP_WAIT2()  asm volatile("cp.async.wait_group 2;"  ::: "memory")
#define CP_WAIT3()  asm volatile("cp.async.wait_group 3;"  ::: "memory")

// ---------------------------------------------------------------------------
// Job descriptor: one 64x64-output GEMM + cell update
// ---------------------------------------------------------------------------
struct Job {
    const __half *A0, *A1;     // A segments (switch at chunk 16)
    size_t s0, s1;             // row strides (halves)
    const __half* W;           // packed weights, row stride Kw
    size_t Kw;
    int nch;
    const float* biasp;
    float* cseg;               // smem c-state [64*16]
    __half* hout;              // global h out: (m0+m)*Hn + j
};

// Chunk load: A 64x64 + W 64x64 fp16, SW128. 4 cp16/thread.
__device__ __forceinline__ void load_cc(const Job* jobs, int cc0, int cc,
                                        uint32_t sb, int tid) {
    const Job& J = jobs[cc >= cc0 ? 1 : 0];
    int lc = (cc >= cc0) ? cc - cc0 : cc;
    const __half* A; size_t As; int kc;
    if (lc < 16) { A = J.A0; As = J.s0; kc = lc * 64; }
    else         { A = J.A1; As = J.s1; kc = (lc - 16) * 64; }
    uint32_t sbase = sb + (cc % NSTAGE) * STAGEB;
    int wk = lc * 64;
#pragma unroll
    for (int j = 0; j < 2; j++) {
        int idx = tid + j * 256;
        int r = idx >> 3, q = idx & 7;
        uint32_t sw = SWZ128(r * 128 + q * 16);
        cp16(sbase + ST_A + sw, A + (size_t)r * As + kc + q * 8);
        cp16(sbase + ST_W + sw, J.W + (size_t)r * J.Kw + wk + q * 8);
    }
    CP_COMMIT();
}

// One K=64 chunk, single pass: 12 LDSM + 16 HMMA per warp (warp tile 16x32).
__device__ __forceinline__ void mma_chunk1(uint32_t st, int wm, int wn, int lane,
                                           float acc[4][4]) {
#pragma unroll
    for (int ks = 0; ks < 4; ks++) {
        int arow = wm * 16 + (lane & 15);
        int akb  = (ks * 16 + (lane >> 4) * 8) * 2;
        uint32_t a[4];
        ldsm4(a, st + ST_A + SWZ128(arow * 128 + akb));
#pragma unroll
        for (int nb = 0; nb < 2; nb++) {
            int brow = wn * 32 + nb * 16 + (lane & 15);
            uint32_t b[4];
            ldsm4(b, st + ST_W + SWZ128(brow * 128 + akb));
            hmma16(acc[nb * 2 + 0], a, b[0], b[2]);
            hmma16(acc[nb * 2 + 1], a, b[1], b[3]);
        }
    }
}

// acc -> Sg (dedicated buffer) -> gates -> cell update -> h write (fp16).
__device__ __forceinline__ void epilogue_cell(
    char* smem, float acc[4][4], int wm, int wn, int lane, int tid,
    const Job& J, int m0, int p0)
{
    float (*Sg)[68] = (float(*)[68])(smem + SMEM_SG);
#pragma unroll
    for (int nb = 0; nb < 2; nb++)
#pragma unroll
        for (int g = 0; g < 2; g++) {
            int f  = nb * 2 + g;
            int cc = wn * 32 + nb * 16 + g * 8 + (lane & 3) * 2;
            int rr = wm * 16 + (lane >> 2);
            Sg[rr][cc]         = acc[f][0];
            Sg[rr][cc + 1]     = acc[f][1];
            Sg[rr + 8][cc]     = acc[f][2];
            Sg[rr + 8][cc + 1] = acc[f][3];
        }
    __syncthreads();
#pragma unroll
    for (int i = 0; i < 4; i++) {
        int lin = tid + i * 256;
        int m = lin >> 4, u = lin & 15;
        int b = m0 + m;
        int col = u * 4;
        float pi_ = Sg[m][col]     + J.biasp[p0 + col];
        float pf  = Sg[m][col + 1] + J.biasp[p0 + col + 1];
        float pg  = Sg[m][col + 2] + J.biasp[p0 + col + 2];
        float po  = Sg[m][col + 3] + J.biasp[p0 + col + 3];
        int ci = m * 16 + u;
        float co = J.cseg[ci];
        float ii = 1.f / (1.f + expf(-pi_));
        float ff = 1.f / (1.f + expf(-pf));
        float gg = tanhf(pg);
        float oo = 1.f / (1.f + expf(-po));
        float cn = ff * co + ii * gg;
        float h  = oo * tanhf(cn);
        J.cseg[ci] = cn;
        int j = (p0 >> 2) + u;
        J.hout[(size_t)b * Hn + j] = __float2half(h);
    }
}

// Run one phase: up to 2 jobs through a single continuous cp.async ring.
__device__ void phase_exec(const Job* jobs, int njobs, char* smem, uint32_t sb,
                           int tid, int wm, int wn, int lane, int m0, int p0) {
    const int cc0 = jobs[0].nch;
    const int TOT = cc0 + (njobs > 1 ? jobs[1].nch : 0);
    float acc[4][4];
#pragma unroll
    for (int r = 0; r < 4; r++)
#pragma unroll
        for (int c = 0; c < 4; c++) acc[r][c] = 0.f;

    int committed = 0;
    for (; committed < NSTAGE - 1; committed++)
        load_cc(jobs, cc0, committed, sb, tid);

    for (int c = 0; c < TOT; c++) {
        // chunk c complete  <=>  pending groups <= committed - c - 1
        int pend = committed - c - 1;
        if (pend <= 0)      { CP_WAIT0(); }
        else if (pend == 1) { CP_WAIT1(); }
        else if (pend == 2) { CP_WAIT2(); }
        else                { CP_WAIT3(); }   // conservative for pend >= 3
        __syncthreads();
        mma_chunk1(sb + (c % NSTAGE) * STAGEB, wm, wn, lane, acc);
        if (c == cc0 - 1) {
            epilogue_cell(smem, acc, wm, wn, lane, tid, jobs[0], m0, p0);
#pragma unroll
            for (int r = 0; r < 4; r++)
#pragma unroll
                for (int cl = 0; cl < 4; cl++) acc[r][cl] = 0.f;
        } else if (c == TOT - 1) {
            epilogue_cell(smem, acc, wm, wn, lane, tid, jobs[1], m0, p0);
        }
        if (committed < TOT) { load_cc(jobs, cc0, committed, sb, tid); committed++; }
    }
    __syncthreads();
}

// Grid-wide barrier (128 co-resident CTAs; monotone counter)
__device__ __forceinline__ void grid_bar(unsigned target) {
    __syncthreads();
    if (threadIdx.x == 0) {
        __threadfence();
        atomicAdd(&g_bar, 1u);
        while (*(volatile unsigned int*)&g_bar < target) { __nanosleep(32); }
        __threadfence();
    }
    __syncthreads();
}

// ---------------------------------------------------------------------------
// Prep kernels
// ---------------------------------------------------------------------------
__global__ void cvt_X_kernel(const float* __restrict__ X) {
    size_t i = (size_t)blockIdx.x * blockDim.x + threadIdx.x;
    if (i < (size_t)Bn * Tn * DIN) g_X[i] = __float2half(X[i]);
}
// W0 packed: row p = 4j+g, cols [0,1024)=W_hh0, [1024,1536)=W_ih0
__global__ void pack_w0_kernel(const float* __restrict__ Wih,
                               const float* __restrict__ Whh) {
    size_t i = (size_t)blockIdx.x * blockDim.x + threadIdx.x;
    if (i >= (size_t)G4 * K0) return;
    int p = (int)(i / K0), k = (int)(i % K0);
    int j = p >> 2, g = p & 3;
    float v = (k < Hn) ? Whh[(size_t)(g * Hn + j) * Hn + k]
                       : Wih[(size_t)(g * Hn + j) * DIN + (k - Hn)];
    g_W0[i] = __float2half(v);
}
// W1 packed: cols [0,1024)=W_ih1 (input = h0), [1024,2048)=W_hh1
__global__ void pack_w1_kernel(const float* __restrict__ Wih,
                               const float* __restrict__ Whh) {
    size_t i = (size_t)blockIdx.x * blockDim.x + threadIdx.x;
    if (i >= (size_t)G4 * K1) return;
    int p = (int)(i / K1), k = (int)(i % K1);
    int j = p >> 2, g = p & 3;
    float v = (k < Hn) ? Wih[(size_t)(g * Hn + j) * Hn + k]
                       : Whh[(size_t)(g * Hn + j) * Hn + (k - Hn)];
    g_W1[i] = __float2half(v);
}
__global__ void pack_bias_kernel(const float* __restrict__ bi0, const float* __restrict__ bh0,
                                 const float* __restrict__ bi1, const float* __restrict__ bh1) {
    int p = blockIdx.x * blockDim.x + threadIdx.x;
    if (p >= G4) return;
    int j = p >> 2, g = p & 3;
    g_b0p[p] = bi0[g * Hn + j] + bh0[g * Hn + j];
    g_b1p[p] = bi1[g * Hn + j] + bh1[g * Hn + j];
}
__global__ void init_state_kernel() {
    int i = blockIdx.x * blockDim.x + threadIdx.x;
    __half z = __float2half(0.f);
    if (i < Bn * Hn) {
        g_h0[0][i] = z; g_h0[1][i] = z;
        g_h1[0][i] = z; g_h1[1][i] = z;
    }
    if (i == 0) g_bar = 0u;
}

// ---------------------------------------------------------------------------
// Persistent LSTM: 128 CTAs; phase = {layer1(t), layer0(t+1)}; 1 barrier/phase.
// CTA (ntile, mh) owns gate cols [ntile*64,+64) and batch rows [mh*64,+64).
// ---------------------------------------------------------------------------
__global__ __launch_bounds__(256, 1) void lstm_persistent() {
    extern __shared__ char smem[];
    uint32_t sb = smem_u32(smem);
    const int tid = threadIdx.x, lane = tid & 31, wid = tid >> 5;
    const int wm = wid & 3, wn = wid >> 2;
    const int ntile = blockIdx.x >> 1, mh = blockIdx.x & 1;
    const int p0 = ntile * 64, m0 = mh * 64;
    float* cs0 = (float*)(smem + SMEM_CS);
    float* cs1 = cs0 + 1024;
    for (int i = tid; i < 2048; i += 256) cs0[i] = 0.f;
    __syncthreads();

    const size_t XS = (size_t)Tn * DIN;
    const __half* W0 = g_W0 + (size_t)p0 * K0;
    const __half* W1 = g_W1 + (size_t)p0 * K1;
    const size_t mh0 = (size_t)m0 * Hn;
    const size_t mhX = (size_t)m0 * XS;

    unsigned bar = 0;
    Job jb[2];

    // initial layer0(0): A=[h0[1](zeros); X(0)] -> h0[0]
    jb[0].A0 = g_h0[1] + mh0; jb[0].A1 = g_X + mhX;
    jb[0].s0 = Hn; jb[0].s1 = XS;
    jb[0].W = W0; jb[0].Kw = K0; jb[0].nch = NCH0;
    jb[0].biasp = g_b0p; jb[0].cseg = cs0; jb[0].hout = g_h0[0];
    phase_exec(jb, 1, smem, sb, tid, wm, wn, lane, m0, p0);
    grid_bar(++bar * NCTA);

    for (int t = 0; t < Tn - 1; t++) {
        const int pc = t & 1, pn = (t + 1) & 1;
        // job0: layer1(t): A=[h0[pc]; h1[pn]] -> h1[pc]
        jb[0].A0 = g_h0[pc] + mh0; jb[0].A1 = g_h1[pn] + mh0;
        jb[0].s0 = Hn; jb[0].s1 = Hn;
        jb[0].W = W1; jb[0].Kw = K1; jb[0].nch = NCH1;
        jb[0].biasp = g_b1p; jb[0].cseg = cs1; jb[0].hout = g_h1[pc];
        // job1: layer0(t+1): A=[h0[pc]; X(t+1)] -> h0[pn]
        jb[1].A0 = g_h0[pc] + mh0;
        jb[1].A1 = g_X + (size_t)(t + 1) * DIN + mhX;
        jb[1].s0 = Hn; jb[1].s1 = XS;
        jb[1].W = W0; jb[1].Kw = K0; jb[1].nch = NCH0;
        jb[1].biasp = g_b0p; jb[1].cseg = cs0; jb[1].hout = g_h0[pn];
        phase_exec(jb, 2, smem, sb, tid, wm, wn, lane, m0, p0);
        grid_bar(++bar * NCTA);
    }

    // final layer1(255): pc=1, pn=0 -> h1[1]
    jb[0].A0 = g_h0[1] + mh0; jb[0].A1 = g_h1[0] + mh0;
    jb[0].s0 = Hn; jb[0].s1 = Hn;
    jb[0].W = W1; jb[0].Kw = K1; jb[0].nch = NCH1;
    jb[0].biasp = g_b1p; jb[0].cseg = cs1; jb[0].hout = g_h1[1];
    phase_exec(jb, 1, smem, sb, tid, wm, wn, lane, m0, p0);
}

// ---------------------------------------------------------------------------
// Final head: out[b][r] = elu(h1(255)[b] . W_br[r] + b_br[r])
// ---------------------------------------------------------------------------
__global__ void br_kernel(const float* __restrict__ Wbr,
                          const float* __restrict__ bbr,
                          float* __restrict__ out) {
    __shared__ float hs[Hn];
    const int b = blockIdx.x;
    const __half* h1 = g_h1[1] + (size_t)b * Hn;
    for (int k = threadIdx.x; k < Hn; k += 256) hs[k] = __half2float(h1[k]);
    __syncthreads();
    const int r = threadIdx.x;
    float acc = bbr[r];
    const float* w = Wbr + (size_t)r * Hn;
    for (int k = 0; k < Hn; k += 4) {
        float4 wv = *reinterpret_cast<const float4*>(w + k);
        float4 hv = *reinterpret_cast<const float4*>(&hs[k]);
        acc += wv.x * hv.x + wv.y * hv.y + wv.z * hv.z + wv.w * hv.w;
    }
    out[b * BRn + r] = acc > 0.f ? acc : expm1f(acc);
}

// ---------------------------------------------------------------------------
extern "C" void kernel_launch(void* const* d_in, const int* in_sizes, int n_in,
                              void* d_out, int out_size) {
    const float* X     = (const float*)d_in[0];
    const float* W_ih0 = (const float*)d_in[1];
    const float* W_hh0 = (const float*)d_in[2];
    const float* b_ih0 = (const float*)d_in[3];
    const float* b_hh0 = (const float*)d_in[4];
    const float* W_ih1 = (const float*)d_in[5];
    const float* W_hh1 = (const float*)d_in[6];
    const float* b_ih1 = (const float*)d_in[7];
    const float* b_hh1 = (const float*)d_in[8];
    const float* W_br  = (const float*)d_in[9];
    const float* b_br  = (const float*)d_in[10];
    float* out = (float*)d_out;

    cudaFuncSetAttribute(lstm_persistent, cudaFuncAttributeMaxDynamicSharedMemorySize,
                         SMEM_BYTES);

    cvt_X_kernel<<<(Bn * Tn * DIN) / 256, 256>>>(X);
    pack_w0_kernel<<<((int)((size_t)G4 * K0 / 256)), 256>>>(W_ih0, W_hh0);
    pack_w1_kernel<<<((int)((size_t)G4 * K1 / 256)), 256>>>(W_ih1, W_hh1);
    pack_bias_kernel<<<G4 / 256, 256>>>(b_ih0, b_hh0, b_ih1, b_hh1);
    init_state_kernel<<<(Bn * Hn) / 256, 256>>>();

    lstm_persistent<<<NCTA, 256, SMEM_BYTES>>>();

    br_kernel<<<Bn, 256>>>(W_br, b_br, out);
}

// round 8
// speedup vs baseline: 6.0656x; 1.0089x over previous
#include <cuda_runtime.h>
#include <cuda_fp16.h>
#include <math.h>
#include <stdint.h>

#define Bn   128
#define Tn   256
#define DIN  512
#define Hn   1024
#define G4   4096
#define BRn  256

#define K0   1536            // layer0 concat K: [h0(1024) | x(512)]
#define K1   2048            // layer1 concat K: [h0(1024) | h1(1024)]
#define NCH0 24
#define NCH1 32

#define NSTAGE 6
#define ST_A   0
#define ST_W   8192
#define STAGEB 16384
#define SMEM_STAGES (NSTAGE * STAGEB)        // 98304
#define SMEM_SG  SMEM_STAGES                 // float Sg[64][68] = 17408
#define SMEM_CS  (SMEM_SG + 17408)           // c-state 2*64*16 f32 = 8192
#define SMEM_BYTES (SMEM_CS + 8192)          // 123904
#define NCTA 128
#define NPRE 4                                // W-prefetch chunks across barrier

#define SWZ128(o) ((o) ^ (((o) >> 3) & 0x70))

// ---------------------------------------------------------------------------
// Device scratch
// ---------------------------------------------------------------------------
__device__ __half g_X[(size_t)Bn * Tn * DIN];
__device__ __half g_W0[(size_t)G4 * K0];     // packed: row p=4j+g, [W_hh0 | W_ih0]
__device__ __half g_W1[(size_t)G4 * K1];     // packed: [W_ih1 | W_hh1]
__device__ float  g_b0p[G4], g_b1p[G4];
__device__ __half g_h0[2][Bn * Hn];
__device__ __half g_h1[2][Bn * Hn];
__device__ unsigned int g_bar;

// ---------------------------------------------------------------------------
// Primitives
// ---------------------------------------------------------------------------
__device__ __forceinline__ uint32_t smem_u32(const void* p) {
    uint32_t a;
    asm("{ .reg .u64 t; cvta.to.shared.u64 t, %1; cvt.u32.u64 %0, t; }"
        : "=r"(a) : "l"(p));
    return a;
}
__device__ __forceinline__ void ldsm4(uint32_t* r, uint32_t addr) {
    asm volatile("ldmatrix.sync.aligned.m8n8.x4.shared.b16 {%0,%1,%2,%3}, [%4];"
                 : "=r"(r[0]), "=r"(r[1]), "=r"(r[2]), "=r"(r[3]) : "r"(addr));
}
__device__ __forceinline__ void hmma16(float* d, const uint32_t* a, uint32_t b0, uint32_t b1) {
    asm volatile("mma.sync.aligned.m16n8k16.row.col.f32.f16.f16.f32 "
                 "{%0,%1,%2,%3}, {%4,%5,%6,%7}, {%8,%9}, {%0,%1,%2,%3};"
                 : "+f"(d[0]), "+f"(d[1]), "+f"(d[2]), "+f"(d[3])
                 : "r"(a[0]), "r"(a[1]), "r"(a[2]), "r"(a[3]), "r"(b0), "r"(b1));
}
__device__ __forceinline__ void cp16(uint32_t so, const void* g) {
    asm volatile("cp.async.cg.shared.global [%0], [%1], 16;" :: "r"(so), "l"(g));
}
#define CP_COMMIT() asm volatile("cp.async.commit_group;" ::: "memory")
__device__ __forceinline__ void cp_wait_n(int pend) {
    switch (pend) {
        case 0:  asm volatile("cp.async.wait_group 0;" ::: "memory"); break;
        case 1:  asm volatile("cp.async.wait_group 1;" ::: "memory"); break;
        case 2:  asm volatile("cp.async.wait_group 2;" ::: "memory"); break;
        case 3:  asm volatile("cp.async.wait_group 3;" ::: "memory"); break;
        default: asm volatile("cp.async.wait_group 4;" ::: "memory"); break;
    }
}

__device__ __forceinline__ float fsigmoid(float x) {
    return __fdividef(1.f, 1.f + __expf(-x));
}
__device__ __forceinline__ float ftanh_(float x) {
    return 2.f * __fdividef(1.f, 1.f + __expf(-2.f * x)) - 1.f;
}

// ---------------------------------------------------------------------------
// Job descriptor
// ---------------------------------------------------------------------------
struct Job {
    const __half *A0, *A1;     // A segments (switch at chunk 16)
    size_t s0, s1;             // row strides
    const __half* W;           // packed weights, row stride Kw
    size_t Kw;
    int nch;
    const float* biasp;
    float* cseg;
    __half* hout;
};

__device__ __forceinline__ void job_chunk_A(const Job* jobs, int cc0, int cc,
                                            const __half*& A, size_t& As, int& kc) {
    const Job& J = jobs[cc >= cc0 ? 1 : 0];
    int lc = (cc >= cc0) ? cc - cc0 : cc;
    if (lc < 16) { A = J.A0; As = J.s0; kc = lc * 64; }
    else         { A = J.A1; As = J.s1; kc = (lc - 16) * 64; }
}

// Fused A+W chunk load (1 commit group). 4 cp16/thread.
__device__ __forceinline__ void load_cc(const Job* jobs, int cc0, int cc,
                                        uint32_t sb, int tid) {
    const Job& J = jobs[cc >= cc0 ? 1 : 0];
    int lc = (cc >= cc0) ? cc - cc0 : cc;
    const __half* A; size_t As; int kc;
    job_chunk_A(jobs, cc0, cc, A, As, kc);
    uint32_t sbase = sb + (cc % NSTAGE) * STAGEB;
    int wk = lc * 64;
#pragma unroll
    for (int j = 0; j < 2; j++) {
        int idx = tid + j * 256;
        int r = idx >> 3, q = idx & 7;
        uint32_t sw = SWZ128(r * 128 + q * 16);
        cp16(sbase + ST_A + sw, A + (size_t)r * As + kc + q * 8);
        cp16(sbase + ST_W + sw, J.W + (size_t)r * J.Kw + wk + q * 8);
    }
    CP_COMMIT();
}

// A-only load for chunk cc (1 commit group).
__device__ __forceinline__ void load_A(const Job* jobs, int cc0, int cc,
                                       uint32_t sb, int tid) {
    const __half* A; size_t As; int kc;
    job_chunk_A(jobs, cc0, cc, A, As, kc);
    uint32_t sbase = sb + (cc % NSTAGE) * STAGEB;
#pragma unroll
    for (int j = 0; j < 2; j++) {
        int idx = tid + j * 256;
        int r = idx >> 3, q = idx & 7;
        cp16(sbase + ST_A + SWZ128(r * 128 + q * 16),
             A + (size_t)r * As + kc + q * 8);
    }
    CP_COMMIT();
}

// W-only prefetch of chunks 0..NPRE-1 of the NEXT phase (NPRE commit groups).
// Safe pre-barrier: W does not depend on other CTAs' current-phase writes.
__device__ __forceinline__ void preload_W(const Job* jobs, int cc0,
                                          uint32_t sb, int tid) {
#pragma unroll
    for (int cc = 0; cc < NPRE; cc++) {
        const Job& J = jobs[cc >= cc0 ? 1 : 0];
        int lc = (cc >= cc0) ? cc - cc0 : cc;
        uint32_t sbase = sb + (cc % NSTAGE) * STAGEB;
        int wk = lc * 64;
#pragma unroll
        for (int j = 0; j < 2; j++) {
            int idx = tid + j * 256;
            int r = idx >> 3, q = idx & 7;
            cp16(sbase + ST_W + SWZ128(r * 128 + q * 16),
                 J.W + (size_t)r * J.Kw + wk + q * 8);
        }
        CP_COMMIT();
    }
}

// One K=64 chunk, single pass: 12 LDSM + 16 HMMA per warp (warp tile 16x32).
__device__ __forceinline__ void mma_chunk1(uint32_t st, int wm, int wn, int lane,
                                           float acc[4][4]) {
#pragma unroll
    for (int ks = 0; ks < 4; ks++) {
        int arow = wm * 16 + (lane & 15);
        int akb  = (ks * 16 + (lane >> 4) * 8) * 2;
        uint32_t a[4];
        ldsm4(a, st + ST_A + SWZ128(arow * 128 + akb));
#pragma unroll
        for (int nb = 0; nb < 2; nb++) {
            int brow = wn * 32 + nb * 16 + (lane & 15);
            uint32_t b[4];
            ldsm4(b, st + ST_W + SWZ128(brow * 128 + akb));
            hmma16(acc[nb * 2 + 0], a, b[0], b[2]);
            hmma16(acc[nb * 2 + 1], a, b[1], b[3]);
        }
    }
}

// acc -> Sg -> gates -> cell update -> h write (fp16).
__device__ __forceinline__ void epilogue_cell(
    char* smem, float acc[4][4], int wm, int wn, int lane, int tid,
    const Job& J, int m0, int p0)
{
    float (*Sg)[68] = (float(*)[68])(smem + SMEM_SG);
#pragma unroll
    for (int nb = 0; nb < 2; nb++)
#pragma unroll
        for (int g = 0; g < 2; g++) {
            int f  = nb * 2 + g;
            int cc = wn * 32 + nb * 16 + g * 8 + (lane & 3) * 2;
            int rr = wm * 16 + (lane >> 2);
            Sg[rr][cc]         = acc[f][0];
            Sg[rr][cc + 1]     = acc[f][1];
            Sg[rr + 8][cc]     = acc[f][2];
            Sg[rr + 8][cc + 1] = acc[f][3];
        }
    __syncthreads();
#pragma unroll
    for (int i = 0; i < 4; i++) {
        int lin = tid + i * 256;
        int m = lin >> 4, u = lin & 15;
        int b = m0 + m;
        int col = u * 4;
        float pi_ = Sg[m][col]     + J.biasp[p0 + col];
        float pf  = Sg[m][col + 1] + J.biasp[p0 + col + 1];
        float pg  = Sg[m][col + 2] + J.biasp[p0 + col + 2];
        float po  = Sg[m][col + 3] + J.biasp[p0 + col + 3];
        int ci = m * 16 + u;
        float co = J.cseg[ci];
        float ii = fsigmoid(pi_);
        float ff = fsigmoid(pf);
        float gg = ftanh_(pg);
        float oo = fsigmoid(po);
        float cn = ff * co + ii * gg;
        float h  = oo * ftanh_(cn);
        J.cseg[ci] = cn;
        int j = (p0 >> 2) + u;
        J.hout[(size_t)b * Hn + j] = __float2half(h);
    }
}

// ---------------------------------------------------------------------------
// Phase: up to 2 jobs through one cp.async ring.
// preloaded: W groups of chunks 0..NPRE-1 already committed (stages 0..NPRE-1).
// Group accounting: ready-group index of chunk c = c + goff (goff = NPRE if
// preloaded, else 0); pend = gcnt - ready - 1.
// ---------------------------------------------------------------------------
__device__ void phase_exec(const Job* jobs, int njobs, bool preloaded,
                           char* smem, uint32_t sb,
                           int tid, int wm, int wn, int lane, int m0, int p0) {
    const int cc0 = jobs[0].nch;
    const int TOT = cc0 + (njobs > 1 ? jobs[1].nch : 0);
    float acc[4][4];
#pragma unroll
    for (int r = 0; r < 4; r++)
#pragma unroll
        for (int c = 0; c < 4; c++) acc[r][c] = 0.f;

    int gcnt, goff, nextc;
    if (preloaded) {
        // A for chunks 0..NPRE-1, then fused chunk NPRE -> 5 chunks in flight
#pragma unroll
        for (int c = 0; c < NPRE; c++) load_A(jobs, cc0, c, sb, tid);
        load_cc(jobs, cc0, NPRE, sb, tid);
        gcnt = NPRE /*W*/ + NPRE /*A*/ + 1;
        goff = NPRE;
        nextc = NPRE + 1;
    } else {
#pragma unroll
        for (int c = 0; c < NSTAGE - 1; c++) load_cc(jobs, cc0, c, sb, tid);
        gcnt = NSTAGE - 1;
        goff = 0;
        nextc = NSTAGE - 1;
    }

    for (int c = 0; c < TOT; c++) {
        cp_wait_n(gcnt - (c + goff) - 1);
        __syncthreads();
        mma_chunk1(sb + (c % NSTAGE) * STAGEB, wm, wn, lane, acc);
        if (c == cc0 - 1) {
            epilogue_cell(smem, acc, wm, wn, lane, tid, jobs[0], m0, p0);
#pragma unroll
            for (int r = 0; r < 4; r++)
#pragma unroll
                for (int cl = 0; cl < 4; cl++) acc[r][cl] = 0.f;
        } else if (c == TOT - 1) {
            epilogue_cell(smem, acc, wm, wn, lane, tid, jobs[1], m0, p0);
        }
        if (nextc < TOT) { load_cc(jobs, cc0, nextc, sb, tid); gcnt++; nextc++; }
    }
    __syncthreads();
}

// Grid-wide barrier: tight L2 spin (no nanosleep quantization)
__device__ __forceinline__ void grid_bar(unsigned target) {
    __syncthreads();
    if (threadIdx.x == 0) {
        __threadfence();
        atomicAdd(&g_bar, 1u);
        while (*(volatile unsigned int*)&g_bar < target) { }
        __threadfence();
    }
    __syncthreads();
}

// ---------------------------------------------------------------------------
// Prep kernels
// ---------------------------------------------------------------------------
__global__ void cvt_X_kernel(const float* __restrict__ X) {
    size_t i = (size_t)blockIdx.x * blockDim.x + threadIdx.x;
    if (i < (size_t)Bn * Tn * DIN) g_X[i] = __float2half(X[i]);
}
__global__ void pack_w0_kernel(const float* __restrict__ Wih,
                               const float* __restrict__ Whh) {
    size_t i = (size_t)blockIdx.x * blockDim.x + threadIdx.x;
    if (i >= (size_t)G4 * K0) return;
    int p = (int)(i / K0), k = (int)(i % K0);
    int j = p >> 2, g = p & 3;
    float v = (k < Hn) ? Whh[(size_t)(g * Hn + j) * Hn + k]
                       : Wih[(size_t)(g * Hn + j) * DIN + (k - Hn)];
    g_W0[i] = __float2half(v);
}
__global__ void pack_w1_kernel(const float* __restrict__ Wih,
                               const float* __restrict__ Whh) {
    size_t i = (size_t)blockIdx.x * blockDim.x + threadIdx.x;
    if (i >= (size_t)G4 * K1) return;
    int p = (int)(i / K1), k = (int)(i % K1);
    int j = p >> 2, g = p & 3;
    float v = (k < Hn) ? Wih[(size_t)(g * Hn + j) * Hn + k]
                       : Whh[(size_t)(g * Hn + j) * Hn + (k - Hn)];
    g_W1[i] = __float2half(v);
}
__global__ void pack_bias_kernel(const float* __restrict__ bi0, const float* __restrict__ bh0,
                                 const float* __restrict__ bi1, const float* __restrict__ bh1) {
    int p = blockIdx.x * blockDim.x + threadIdx.x;
    if (p >= G4) return;
    int j = p >> 2, g = p & 3;
    g_b0p[p] = bi0[g * Hn + j] + bh0[g * Hn + j];
    g_b1p[p] = bi1[g * Hn + j] + bh1[g * Hn + j];
}
__global__ void init_state_kernel() {
    int i = blockIdx.x * blockDim.x + threadIdx.x;
    __half z = __float2half(0.f);
    if (i < Bn * Hn) {
        g_h0[0][i] = z; g_h0[1][i] = z;
        g_h1[0][i] = z; g_h1[1][i] = z;
    }
    if (i == 0) g_bar = 0u;
}

// ---------------------------------------------------------------------------
// Persistent LSTM: 128 CTAs; phase = {layer1(t), layer0(t+1)}; 1 barrier/phase
// with W prefetched across the barrier.
// ---------------------------------------------------------------------------
__global__ __launch_bounds__(256, 1) void lstm_persistent() {
    extern __shared__ char smem[];
    uint32_t sb = smem_u32(smem);
    const int tid = threadIdx.x, lane = tid & 31, wid = tid >> 5;
    const int wm = wid & 3, wn = wid >> 2;
    const int ntile = blockIdx.x >> 1, mh = blockIdx.x & 1;
    const int p0 = ntile * 64, m0 = mh * 64;
    float* cs0 = (float*)(smem + SMEM_CS);
    float* cs1 = cs0 + 1024;
    for (int i = tid; i < 2048; i += 256) cs0[i] = 0.f;
    __syncthreads();

    const size_t XS = (size_t)Tn * DIN;
    const __half* W0 = g_W0 + (size_t)p0 * K0;
    const __half* W1 = g_W1 + (size_t)p0 * K1;
    const size_t mh0 = (size_t)m0 * Hn;
    const size_t mhX = (size_t)m0 * XS;

    unsigned bar = 0;
    Job jb[2], jbn[2];

    // initial layer0(0): A=[h0[1](zeros); X(0)] -> h0[0]
    jb[0].A0 = g_h0[1] + mh0; jb[0].A1 = g_X + mhX;
    jb[0].s0 = Hn; jb[0].s1 = XS;
    jb[0].W = W0; jb[0].Kw = K0; jb[0].nch = NCH0;
    jb[0].biasp = g_b0p; jb[0].cseg = cs0; jb[0].hout = g_h0[0];
    phase_exec(jb, 1, false, smem, sb, tid, wm, wn, lane, m0, p0);

    // set up phase t=0, prefetch its W, barrier
    auto setup_phase = [&](Job* J, int t) {
        const int pc = t & 1, pn = (t + 1) & 1;
        J[0].A0 = g_h0[pc] + mh0; J[0].A1 = g_h1[pn] + mh0;
        J[0].s0 = Hn; J[0].s1 = Hn;
        J[0].W = W1; J[0].Kw = K1; J[0].nch = NCH1;
        J[0].biasp = g_b1p; J[0].cseg = cs1; J[0].hout = g_h1[pc];
        J[1].A0 = g_h0[pc] + mh0;
        J[1].A1 = g_X + (size_t)(t + 1) * DIN + mhX;
        J[1].s0 = Hn; J[1].s1 = XS;
        J[1].W = W0; J[1].Kw = K0; J[1].nch = NCH0;
        J[1].biasp = g_b0p; J[1].cseg = cs0; J[1].hout = g_h0[pn];
    };

    setup_phase(jb, 0);
    preload_W(jb, jb[0].nch, sb, tid);
    grid_bar(++bar * NCTA);

    for (int t = 0; t < Tn - 1; t++) {
        phase_exec(jb, 2, true, smem, sb, tid, wm, wn, lane, m0, p0);
        // prepare next phase (or final) and prefetch its W pre-barrier
        if (t + 1 < Tn - 1) {
            setup_phase(jbn, t + 1);
            preload_W(jbn, jbn[0].nch, sb, tid);
        } else {
            // final phase: layer1(255): A=[h0[1]; h1[0]] -> h1[1]
            jbn[0].A0 = g_h0[1] + mh0; jbn[0].A1 = g_h1[0] + mh0;
            jbn[0].s0 = Hn; jbn[0].s1 = Hn;
            jbn[0].W = W1; jbn[0].Kw = K1; jbn[0].nch = NCH1;
            jbn[0].biasp = g_b1p; jbn[0].cseg = cs1; jbn[0].hout = g_h1[1];
            preload_W(jbn, jbn[0].nch, sb, tid);
        }
        grid_bar(++bar * NCTA);
        jb[0] = jbn[0]; jb[1] = jbn[1];
    }

    phase_exec(jb, 1, true, smem, sb, tid, wm, wn, lane, m0, p0);
}

// ---------------------------------------------------------------------------
// Final head: out[b][r] = elu(h1(255)[b] . W_br[r] + b_br[r])
// ---------------------------------------------------------------------------
__global__ void br_kernel(const float* __restrict__ Wbr,
                          const float* __restrict__ bbr,
                          float* __restrict__ out) {
    __shared__ float hs[Hn];
    const int b = blockIdx.x;
    const __half* h1 = g_h1[1] + (size_t)b * Hn;
    for (int k = threadIdx.x; k < Hn; k += 256) hs[k] = __half2float(h1[k]);
    __syncthreads();
    const int r = threadIdx.x;
    float acc = bbr[r];
    const float* w = Wbr + (size_t)r * Hn;
    for (int k = 0; k < Hn; k += 4) {
        float4 wv = *reinterpret_cast<const float4*>(w + k);
        float4 hv = *reinterpret_cast<const float4*>(&hs[k]);
        acc += wv.x * hv.x + wv.y * hv.y + wv.z * hv.z + wv.w * hv.w;
    }
    out[b * BRn + r] = acc > 0.f ? acc : expm1f(acc);
}

// ---------------------------------------------------------------------------
extern "C" void kernel_launch(void* const* d_in, const int* in_sizes, int n_in,
                              void* d_out, int out_size) {
    const float* X     = (const float*)d_in[0];
    const float* W_ih0 = (const float*)d_in[1];
    const float* W_hh0 = (const float*)d_in[2];
    const float* b_ih0 = (const float*)d_in[3];
    const float* b_hh0 = (const float*)d_in[4];
    const float* W_ih1 = (const float*)d_in[5];
    const float* W_hh1 = (const float*)d_in[6];
    const float* b_ih1 = (const float*)d_in[7];
    const float* b_hh1 = (const float*)d_in[8];
    const float* W_br  = (const float*)d_in[9];
    const float* b_br  = (const float*)d_in[10];
    float* out = (float*)d_out;

    cudaFuncSetAttribute(lstm_persistent, cudaFuncAttributeMaxDynamicSharedMemorySize,
                         SMEM_BYTES);

    cvt_X_kernel<<<(Bn * Tn * DIN) / 256, 256>>>(X);
    pack_w0_kernel<<<((int)((size_t)G4 * K0 / 256)), 256>>>(W_ih0, W_hh0);
    pack_w1_kernel<<<((int)((size_t)G4 * K1 / 256)), 256>>>(W_ih1, W_hh1);
    pack_bias_kernel<<<G4 / 256, 256>>>(b_ih0, b_hh0, b_ih1, b_hh1);
    init_state_kernel<<<(Bn * Hn) / 256, 256>>>();

    lstm_persistent<<<NCTA, 256, SMEM_BYTES>>>();

    br_kernel<<<Bn, 256>>>(W_br, b_br, out);
}

// round 10
// speedup vs baseline: 7.1540x; 1.1795x over previous
#include <cuda_runtime.h>
#include <cuda_fp16.h>
#include <math.h>
#include <stdint.h>

#define Bn   128
#define Tn   256
#define DIN  512
#define Hn   1024
#define G4   4096
#define BRn  256

#define K0   1536
#define K1   2048
#define NCH0 24
#define NCH1 32

#define NSTAGE 6
#define ST_A   0
#define ST_W   8192
#define STAGEB 16384
#define BLK    16384                         // A-block stride (h jc-block / X kc-block)
#define SMEM_STAGES (NSTAGE * STAGEB)        // 98304
#define SMEM_SG  SMEM_STAGES                 // float Sg[64][68] = 17408
#define SMEM_CS  (SMEM_SG + 17408)           // c-state 2*64*16 f32 = 8192
#define SMEM_MB  (SMEM_CS + 8192)            // 6 mbarriers
#define SMEM_BYTES (SMEM_MB + 64)
#define NCTA 128

#define SWZ128(o) ((o) ^ (((o) >> 3) & 0x70))

// ---------------------------------------------------------------------------
// Device scratch — all GEMM operands pre-packed as SW128-swizzled 8KB blocks
// ---------------------------------------------------------------------------
__device__ __align__(1024) unsigned char g_Xp[(size_t)Tn * 8 * 16384];      // [t][kc][swz(b*128+col*2)]
__device__ __align__(1024) unsigned char g_W0p[(size_t)64 * NCH0 * 8192];   // [ntile][kc][swz(r*128+col*2)]
__device__ __align__(1024) unsigned char g_W1p[(size_t)64 * NCH1 * 8192];
__device__ __align__(1024) unsigned char g_h0p[2][16 * 16384];              // [jc][swz(b*128+jl*2)]
__device__ __align__(1024) unsigned char g_h1p[2][16 * 16384];
__device__ float g_b0p[G4], g_b1p[G4];
__device__ unsigned int g_bar;

// ---------------------------------------------------------------------------
// Primitives
// ---------------------------------------------------------------------------
__device__ __forceinline__ uint32_t smem_u32(const void* p) {
    uint32_t a;
    asm("{ .reg .u64 t; cvta.to.shared.u64 t, %1; cvt.u32.u64 %0, t; }"
        : "=r"(a) : "l"(p));
    return a;
}
__device__ __forceinline__ void ldsm4(uint32_t* r, uint32_t addr) {
    asm volatile("ldmatrix.sync.aligned.m8n8.x4.shared.b16 {%0,%1,%2,%3}, [%4];"
                 : "=r"(r[0]), "=r"(r[1]), "=r"(r[2]), "=r"(r[3]) : "r"(addr));
}
__device__ __forceinline__ void hmma16(float* d, const uint32_t* a, uint32_t b0, uint32_t b1) {
    asm volatile("mma.sync.aligned.m16n8k16.row.col.f32.f16.f16.f32 "
                 "{%0,%1,%2,%3}, {%4,%5,%6,%7}, {%8,%9}, {%0,%1,%2,%3};"
                 : "+f"(d[0]), "+f"(d[1]), "+f"(d[2]), "+f"(d[3])
                 : "r"(a[0]), "r"(a[1]), "r"(a[2]), "r"(a[3]), "r"(b0), "r"(b1));
}
__device__ __forceinline__ void bulk_g2s(uint32_t dst, const void* src, uint32_t bytes,
                                         uint32_t mbar) {
    asm volatile("cp.async.bulk.shared::cta.global.mbarrier::complete_tx::bytes "
                 "[%0], [%1], %2, [%3];"
                 :: "r"(dst), "l"(src), "r"(bytes), "r"(mbar) : "memory");
}
#define MBARRIER_INIT(mb, c) \
    asm volatile("mbarrier.init.shared.b64 [%0], %1;" :: "r"((uint32_t)(mb)), "r"((uint32_t)(c)) : "memory")
#define MBARRIER_EXPECT_TX(mb, tx) \
    asm volatile("mbarrier.arrive.expect_tx.shared.b64 _, [%0], %1;" :: "r"((uint32_t)(mb)), "r"((uint32_t)(tx)) : "memory")
#define FENCE_PROXY_ASYNC() asm volatile("fence.proxy.async.shared::cta;" ::: "memory")
#define MBARRIER_WAIT_PARITY(mb, par) do {                                         \
    uint32_t _mb = (uint32_t)(mb); uint32_t _p = (uint32_t)(par); uint32_t _d;     \
    asm volatile("{\n\t.reg .pred p;\n\t"                                          \
        "mbarrier.try_wait.parity.acquire.cta.shared::cta.b64 p, [%1], %2;\n\t"    \
        "selp.b32 %0, 1, 0, p;\n\t}" : "=r"(_d) : "r"(_mb), "r"(_p) : "memory");   \
    if (!_d) {                                                                     \
        asm volatile("{\n\t.reg .pred P1;\n\t"                                     \
            "WL_%=:\n\t"                                                           \
            "mbarrier.try_wait.parity.acquire.cta.shared::cta.b64 P1, [%0], %1, 0x989680;\n\t" \
            "@P1 bra.uni WD_%=;\n\t"                                               \
            "bra.uni WL_%=;\n\t"                                                   \
            "WD_%=:\n\t}" :: "r"(_mb), "r"(_p) : "memory");                        \
    }                                                                              \
} while (0)

__device__ __forceinline__ float fsigmoid(float x) {
    return __fdividef(1.f, 1.f + __expf(-x));
}
__device__ __forceinline__ float ftanh_(float x) {
    return 2.f * __fdividef(1.f, 1.f + __expf(-2.f * x)) - 1.f;
}

// ---------------------------------------------------------------------------
// Job descriptor
// ---------------------------------------------------------------------------
struct Job {
    const unsigned char *A0, *A1;   // A chunk-block bases (switch at chunk 16), stride BLK
    const unsigned char *Wb;        // W chunk-block base, stride 8192
    int nch;
    const float* biasp;
    float* cseg;
    unsigned char* hout;            // packed h buffer base
};

// Issue one chunk: expect_tx + 2 bulk copies. Called by tid 0 only.
__device__ __forceinline__ void issue_chunk(const Job* jobs, int cc0, int cc,
                                            unsigned g, uint32_t sb, uint32_t mb) {
    const Job& J = jobs[cc >= cc0 ? 1 : 0];
    int lc = (cc >= cc0) ? cc - cc0 : cc;
    const unsigned char* Ab = (lc < 16) ? J.A0 + (size_t)lc * BLK
                                        : J.A1 + (size_t)(lc - 16) * BLK;
    const unsigned char* Wb = J.Wb + (size_t)lc * 8192;
    uint32_t s    = g % NSTAGE;
    uint32_t mbar = mb + s * 8;
    uint32_t dst  = sb + s * STAGEB;
    MBARRIER_EXPECT_TX(mbar, 16384u);
    bulk_g2s(dst + ST_A, Ab, 8192u, mbar);
    bulk_g2s(dst + ST_W, Wb, 8192u, mbar);
}

// One K=64 chunk, single pass: 12 LDSM + 16 HMMA per warp (warp tile 16x32).
__device__ __forceinline__ void mma_chunk1(uint32_t st, int wm, int wn, int lane,
                                           float acc[4][4]) {
#pragma unroll
    for (int ks = 0; ks < 4; ks++) {
        int arow = wm * 16 + (lane & 15);
        int akb  = (ks * 16 + (lane >> 4) * 8) * 2;
        uint32_t a[4];
        ldsm4(a, st + ST_A + SWZ128(arow * 128 + akb));
#pragma unroll
        for (int nb = 0; nb < 2; nb++) {
            int brow = wn * 32 + nb * 16 + (lane & 15);
            uint32_t b[4];
            ldsm4(b, st + ST_W + SWZ128(brow * 128 + akb));
            hmma16(acc[nb * 2 + 0], a, b[0], b[2]);
            hmma16(acc[nb * 2 + 1], a, b[1], b[3]);
        }
    }
}

// acc -> Sg -> gates -> cell update -> packed swizzled h write.
__device__ __forceinline__ void epilogue_cell(
    char* smem, float acc[4][4], int wm, int wn, int lane, int tid,
    const Job& J, int m0, int p0)
{
    float (*Sg)[68] = (float(*)[68])(smem + SMEM_SG);
#pragma unroll
    for (int nb = 0; nb < 2; nb++)
#pragma unroll
        for (int g = 0; g < 2; g++) {
            int f  = nb * 2 + g;
            int cc = wn * 32 + nb * 16 + g * 8 + (lane & 3) * 2;
            int rr = wm * 16 + (lane >> 2);
            Sg[rr][cc]         = acc[f][0];
            Sg[rr][cc + 1]     = acc[f][1];
            Sg[rr + 8][cc]     = acc[f][2];
            Sg[rr + 8][cc + 1] = acc[f][3];
        }
    __syncthreads();
#pragma unroll
    for (int i = 0; i < 4; i++) {
        int lin = tid + i * 256;
        int m = lin >> 4, u = lin & 15;
        int b = m0 + m;
        int col = u * 4;
        float pi_ = Sg[m][col]     + J.biasp[p0 + col];
        float pf  = Sg[m][col + 1] + J.biasp[p0 + col + 1];
        float pg  = Sg[m][col + 2] + J.biasp[p0 + col + 2];
        float po  = Sg[m][col + 3] + J.biasp[p0 + col + 3];
        int ci = m * 16 + u;
        float co = J.cseg[ci];
        float ii = fsigmoid(pi_);
        float ff = fsigmoid(pf);
        float gg = ftanh_(pg);
        float oo = fsigmoid(po);
        float cn = ff * co + ii * gg;
        float h  = oo * ftanh_(cn);
        J.cseg[ci] = cn;
        int j = (p0 >> 2) + u;                 // global gate unit = ntile*16 + u
        size_t off = (size_t)(j >> 6) * BLK + SWZ128(b * 128 + (j & 63) * 2);
        *(__half*)(J.hout + off) = __float2half(h);
    }
}

// ---------------------------------------------------------------------------
// Phase: up to 2 jobs through the bulk-DMA ring.
// gc = global chunk counter (stage = g%6, mbarrier parity = (g/6)&1).
// ---------------------------------------------------------------------------
__device__ void phase_exec(const Job* jobs, int njobs, unsigned& gcref,
                           char* smem, uint32_t sb, uint32_t mb,
                           int tid, int wm, int wn, int lane, int m0, int p0) {
    const int cc0 = jobs[0].nch;
    const int TOT = cc0 + (njobs > 1 ? jobs[1].nch : 0);
    const unsigned gc = gcref;
    float acc[4][4];
#pragma unroll
    for (int r = 0; r < 4; r++)
#pragma unroll
        for (int c = 0; c < 4; c++) acc[r][c] = 0.f;

    if (tid == 0)
        for (int c = 0; c < NSTAGE - 1; c++)
            issue_chunk(jobs, cc0, c, gc + c, sb, mb);

    for (int c = 0; c < TOT; c++) {
        unsigned g = gc + c;
        uint32_t s = g % NSTAGE;
        MBARRIER_WAIT_PARITY(mb + s * 8, (g / NSTAGE) & 1);
        // safe: end-of-prev-iteration __syncthreads => all warps finished chunk c-1,
        // whose stage is exactly the target of chunk c+5.
        if (tid == 0 && c + NSTAGE - 1 < TOT)
            issue_chunk(jobs, cc0, c + NSTAGE - 1, g + NSTAGE - 1, sb, mb);
        mma_chunk1(sb + s * STAGEB, wm, wn, lane, acc);
        if (c == cc0 - 1) {
            epilogue_cell(smem, acc, wm, wn, lane, tid, jobs[0], m0, p0);
#pragma unroll
            for (int r = 0; r < 4; r++)
#pragma unroll
                for (int cl = 0; cl < 4; cl++) acc[r][cl] = 0.f;
        } else if (c == TOT - 1) {
            epilogue_cell(smem, acc, wm, wn, lane, tid, jobs[1], m0, p0);
        }
        __syncthreads();
    }
    gcref = gc + TOT;
}

// Grid-wide barrier (tight spin)
__device__ __forceinline__ void grid_bar(unsigned target) {
    __syncthreads();
    if (threadIdx.x == 0) {
        __threadfence();
        atomicAdd(&g_bar, 1u);
        while (*(volatile unsigned int*)&g_bar < target) { }
        __threadfence();
    }
    __syncthreads();
}

// ---------------------------------------------------------------------------
// Prep kernels (write PRE-SWIZZLED chunk blocks)
// ---------------------------------------------------------------------------
__global__ void pack_X_kernel(const float* __restrict__ X) {
    size_t i = (size_t)blockIdx.x * blockDim.x + threadIdx.x;
    if (i >= (size_t)Bn * Tn * DIN) return;
    int d = (int)(i % DIN);
    size_t r = i / DIN;
    int t = (int)(r % Tn), b = (int)(r / Tn);
    int kc = d >> 6, col = d & 63;
    size_t off = (size_t)(t * 8 + kc) * BLK + SWZ128(b * 128 + col * 2);
    *(__half*)(g_Xp + off) = __float2half(X[i]);
}
__global__ void pack_w0_kernel(const float* __restrict__ Wih,
                               const float* __restrict__ Whh) {
    size_t i = (size_t)blockIdx.x * blockDim.x + threadIdx.x;
    if (i >= (size_t)G4 * K0) return;
    int p = (int)(i / K0), k = (int)(i % K0);
    int j = p >> 2, g4 = p & 3;
    float v = (k < Hn) ? Whh[(size_t)(g4 * Hn + j) * Hn + k]
                       : Wih[(size_t)(g4 * Hn + j) * DIN + (k - Hn)];
    int nt = p >> 6, rr = p & 63, kc = k >> 6, col = k & 63;
    size_t off = (size_t)(nt * NCH0 + kc) * 8192 + SWZ128(rr * 128 + col * 2);
    *(__half*)(g_W0p + off) = __float2half(v);
}
__global__ void pack_w1_kernel(const float* __restrict__ Wih,
                               const float* __restrict__ Whh) {
    size_t i = (size_t)blockIdx.x * blockDim.x + threadIdx.x;
    if (i >= (size_t)G4 * K1) return;
    int p = (int)(i / K1), k = (int)(i % K1);
    int j = p >> 2, g4 = p & 3;
    float v = (k < Hn) ? Wih[(size_t)(g4 * Hn + j) * Hn + k]
                       : Whh[(size_t)(g4 * Hn + j) * Hn + (k - Hn)];
    int nt = p >> 6, rr = p & 63, kc = k >> 6, col = k & 63;
    size_t off = (size_t)(nt * NCH1 + kc) * 8192 + SWZ128(rr * 128 + col * 2);
    *(__half*)(g_W1p + off) = __float2half(v);
}
__global__ void pack_bias_kernel(const float* __restrict__ bi0, const float* __restrict__ bh0,
                                 const float* __restrict__ bi1, const float* __restrict__ bh1) {
    int p = blockIdx.x * blockDim.x + threadIdx.x;
    if (p >= G4) return;
    int j = p >> 2, g = p & 3;
    g_b0p[p] = bi0[g * Hn + j] + bh0[g * Hn + j];
    g_b1p[p] = bi1[g * Hn + j] + bh1[g * Hn + j];
}
__global__ void init_state_kernel() {
    size_t i = (size_t)blockIdx.x * blockDim.x + threadIdx.x;
    if (i < (size_t)16 * 16384 / 4) {
        ((uint32_t*)g_h0p[0])[i] = 0; ((uint32_t*)g_h0p[1])[i] = 0;
        ((uint32_t*)g_h1p[0])[i] = 0; ((uint32_t*)g_h1p[1])[i] = 0;
    }
    if (i == 0) g_bar = 0u;
}

// ---------------------------------------------------------------------------
// Persistent LSTM: 128 CTAs; phase = {layer1(t), layer0(t+1)}; 1 barrier/phase.
// ---------------------------------------------------------------------------
__global__ __launch_bounds__(256, 1) void lstm_persistent() {
    extern __shared__ char smem[];
    uint32_t sb = smem_u32(smem);
    uint32_t mb = sb + SMEM_MB;
    const int tid = threadIdx.x, lane = tid & 31, wid = tid >> 5;
    const int wm = wid & 3, wn = wid >> 2;
    const int ntile = blockIdx.x >> 1, mh = blockIdx.x & 1;
    const int p0 = ntile * 64, m0 = mh * 64;
    float* cs0 = (float*)(smem + SMEM_CS);
    float* cs1 = cs0 + 1024;
    for (int i = tid; i < 2048; i += 256) cs0[i] = 0.f;
    if (tid == 0) {
        for (int s = 0; s < NSTAGE; s++) MBARRIER_INIT(mb + s * 8, 1);
        FENCE_PROXY_ASYNC();
    }
    __syncthreads();

    const unsigned char* W0b = g_W0p + (size_t)ntile * NCH0 * 8192;
    const unsigned char* W1b = g_W1p + (size_t)ntile * NCH1 * 8192;
    const size_t mo = (size_t)mh * 8192;

    unsigned gc = 0, bar = 0;
    Job jb[2];

    // initial layer0(0): A=[h0[1](zeros); X(0)] -> h0[0]
    jb[0].A0 = g_h0p[1] + mo; jb[0].A1 = g_Xp + mo;
    jb[0].Wb = W0b; jb[0].nch = NCH0;
    jb[0].biasp = g_b0p; jb[0].cseg = cs0; jb[0].hout = g_h0p[0];
    phase_exec(jb, 1, gc, smem, sb, mb, tid, wm, wn, lane, m0, p0);
    grid_bar(++bar * NCTA);

    for (int t = 0; t < Tn - 1; t++) {
        const int pc = t & 1, pn = (t + 1) & 1;
        // job0: layer1(t): A=[h0[pc]; h1[pn]] -> h1[pc]
        jb[0].A0 = g_h0p[pc] + mo; jb[0].A1 = g_h1p[pn] + mo;
        jb[0].Wb = W1b; jb[0].nch = NCH1;
        jb[0].biasp = g_b1p; jb[0].cseg = cs1; jb[0].hout = g_h1p[pc];
        // job1: layer0(t+1): A=[h0[pc]; X(t+1)] -> h0[pn]
        jb[1].A0 = g_h0p[pc] + mo;
        jb[1].A1 = g_Xp + (size_t)(t + 1) * 8 * BLK + mo;
        jb[1].Wb = W0b; jb[1].nch = NCH0;
        jb[1].biasp = g_b0p; jb[1].cseg = cs0; jb[1].hout = g_h0p[pn];
        phase_exec(jb, 2, gc, smem, sb, mb, tid, wm, wn, lane, m0, p0);
        grid_bar(++bar * NCTA);
    }

    // final layer1(255): A=[h0[1]; h1[0]] -> h1[1]
    jb[0].A0 = g_h0p[1] + mo; jb[0].A1 = g_h1p[0] + mo;
    jb[0].Wb = W1b; jb[0].nch = NCH1;
    jb[0].biasp = g_b1p; jb[0].cseg = cs1; jb[0].hout = g_h1p[1];
    phase_exec(jb, 1, gc, smem, sb, mb, tid, wm, wn, lane, m0, p0);
}

// ---------------------------------------------------------------------------
// Final head: out[b][r] = elu(h1(255)[b] . W_br[r] + b_br[r])
// ---------------------------------------------------------------------------
__global__ void br_kernel(const float* __restrict__ Wbr,
                          const float* __restrict__ bbr,
                          float* __restrict__ out) {
    __shared__ float hs[Hn];
    const int b = blockIdx.x;
    for (int k = threadIdx.x; k < Hn; k += 256) {
        size_t off = (size_t)(k >> 6) * BLK + SWZ128(b * 128 + (k & 63) * 2);
        hs[k] = __half2float(*(const __half*)(g_h1p[1] + off));
    }
    __syncthreads();
    const int r = threadIdx.x;
    float acc = bbr[r];
    const float* w = Wbr + (size_t)r * Hn;
    for (int k = 0; k < Hn; k += 4) {
        float4 wv = *reinterpret_cast<const float4*>(w + k);
        float4 hv = *reinterpret_cast<const float4*>(&hs[k]);
        acc += wv.x * hv.x + wv.y * hv.y + wv.z * hv.z + wv.w * hv.w;
    }
    out[b * BRn + r] = acc > 0.f ? acc : expm1f(acc);
}

// ---------------------------------------------------------------------------
extern "C" void kernel_launch(void* const* d_in, const int* in_sizes, int n_in,
                              void* d_out, int out_size) {
    const float* X     = (const float*)d_in[0];
    const float* W_ih0 = (const float*)d_in[1];
    const float* W_hh0 = (const float*)d_in[2];
    const float* b_ih0 = (const float*)d_in[3];
    const float* b_hh0 = (const float*)d_in[4];
    const float* W_ih1 = (const float*)d_in[5];
    const float* W_hh1 = (const float*)d_in[6];
    const float* b_ih1 = (const float*)d_in[7];
    const float* b_hh1 = (const float*)d_in[8];
    const float* W_br  = (const float*)d_in[9];
    const float* b_br  = (const float*)d_in[10];
    float* out = (float*)d_out;

    cudaFuncSetAttribute(lstm_persistent, cudaFuncAttributeMaxDynamicSharedMemorySize,
                         SMEM_BYTES);

    pack_X_kernel<<<(Bn * Tn * DIN) / 256, 256>>>(X);
    pack_w0_kernel<<<((int)((size_t)G4 * K0 / 256)), 256>>>(W_ih0, W_hh0);
    pack_w1_kernel<<<((int)((size_t)G4 * K1 / 256)), 256>>>(W_ih1, W_hh1);
    pack_bias_kernel<<<G4 / 256, 256>>>(b_ih0, b_hh0, b_ih1, b_hh1);
    init_state_kernel<<<256, 256>>>();

    lstm_persistent<<<NCTA, 256, SMEM_BYTES>>>();

    br_kernel<<<Bn, 256>>>(W_br, b_br, out);
}

// round 11
// speedup vs baseline: 8.5581x; 1.1963x over previous
#include <cuda_runtime.h>
#include <cuda_fp16.h>
#include <math.h>
#include <stdint.h>

#define Bn   128
#define Tn   256
#define DIN  512
#define Hn   1024
#define G4   4096
#define BRn  256

#define NCH0 24            // K64 chunks, layer0 (h0:16, X:8)
#define NCH1 32            // K64 chunks, layer1 (h0:16, h1:16)
#define NST0 12            // K128 stages, layer0
#define NST1 16            // K128 stages, layer1

#define NSTAGE 3
#define ST_W   16384
#define STAGEB 32768
#define BLK    16384                         // A-block stride in packed arrays
#define SMEM_STAGES (NSTAGE * STAGEB)        // 98304
#define SMEM_SG  SMEM_STAGES                 // float Sg[64][68] = 17408
#define SMEM_CS  (SMEM_SG + 17408)           // c-state 2*64*16 f32 = 8192
#define SMEM_MB  (SMEM_CS + 8192)
#define SMEM_BYTES (SMEM_MB + 64)            // 123968
#define NCTA 128

#define SWZ128(o) ((o) ^ (((o) >> 3) & 0x70))

// ---------------------------------------------------------------------------
// Device scratch — pre-swizzled blocks (same layout as R10)
// ---------------------------------------------------------------------------
__device__ __align__(1024) unsigned char g_Xp[(size_t)Tn * 8 * 16384];      // [t*8+kc][swz(b*128+col*2)]
__device__ __align__(1024) unsigned char g_W0p[(size_t)64 * NCH0 * 8192];   // [nt*NCH0+kc][swz(r*128+col*2)]
__device__ __align__(1024) unsigned char g_W1p[(size_t)64 * NCH1 * 8192];
__device__ __align__(1024) unsigned char g_h0p[2][16 * 16384];              // [jc][swz(b*128+jl*2)]
__device__ __align__(1024) unsigned char g_h1p[2][16 * 16384];
__device__ float g_b0p[G4], g_b1p[G4];
__device__ unsigned int g_bar;

// ---------------------------------------------------------------------------
// Primitives
// ---------------------------------------------------------------------------
__device__ __forceinline__ uint32_t smem_u32(const void* p) {
    uint32_t a;
    asm("{ .reg .u64 t; cvta.to.shared.u64 t, %1; cvt.u32.u64 %0, t; }"
        : "=r"(a) : "l"(p));
    return a;
}
__device__ __forceinline__ void ldsm4(uint32_t* r, uint32_t addr) {
    asm volatile("ldmatrix.sync.aligned.m8n8.x4.shared.b16 {%0,%1,%2,%3}, [%4];"
                 : "=r"(r[0]), "=r"(r[1]), "=r"(r[2]), "=r"(r[3]) : "r"(addr));
}
__device__ __forceinline__ void hmma16(float* d, const uint32_t* a, uint32_t b0, uint32_t b1) {
    asm volatile("mma.sync.aligned.m16n8k16.row.col.f32.f16.f16.f32 "
                 "{%0,%1,%2,%3}, {%4,%5,%6,%7}, {%8,%9}, {%0,%1,%2,%3};"
                 : "+f"(d[0]), "+f"(d[1]), "+f"(d[2]), "+f"(d[3])
                 : "r"(a[0]), "r"(a[1]), "r"(a[2]), "r"(a[3]), "r"(b0), "r"(b1));
}
__device__ __forceinline__ void bulk_g2s(uint32_t dst, const void* src, uint32_t bytes,
                                         uint32_t mbar) {
    asm volatile("cp.async.bulk.shared::cta.global.mbarrier::complete_tx::bytes "
                 "[%0], [%1], %2, [%3];"
                 :: "r"(dst), "l"(src), "r"(bytes), "r"(mbar) : "memory");
}
#define MBARRIER_INIT(mb, c) \
    asm volatile("mbarrier.init.shared.b64 [%0], %1;" :: "r"((uint32_t)(mb)), "r"((uint32_t)(c)) : "memory")
#define MBARRIER_EXPECT_TX(mb, tx) \
    asm volatile("mbarrier.arrive.expect_tx.shared.b64 _, [%0], %1;" :: "r"((uint32_t)(mb)), "r"((uint32_t)(tx)) : "memory")
#define FENCE_PROXY_ASYNC() asm volatile("fence.proxy.async.shared::cta;" ::: "memory")
#define MBARRIER_WAIT_PARITY(mb, par) do {                                         \
    uint32_t _mb = (uint32_t)(mb); uint32_t _p = (uint32_t)(par); uint32_t _d;     \
    asm volatile("{\n\t.reg .pred p;\n\t"                                          \
        "mbarrier.try_wait.parity.acquire.cta.shared::cta.b64 p, [%1], %2;\n\t"    \
        "selp.b32 %0, 1, 0, p;\n\t}" : "=r"(_d) : "r"(_mb), "r"(_p) : "memory");   \
    if (!_d) {                                                                     \
        asm volatile("{\n\t.reg .pred P1;\n\t"                                     \
            "WL_%=:\n\t"                                                           \
            "mbarrier.try_wait.parity.acquire.cta.shared::cta.b64 P1, [%0], %1, 0x989680;\n\t" \
            "@P1 bra.uni WD_%=;\n\t"                                               \
            "bra.uni WL_%=;\n\t"                                                   \
            "WD_%=:\n\t}" :: "r"(_mb), "r"(_p) : "memory");                        \
    }                                                                              \
} while (0)

__device__ __forceinline__ float fsigmoid(float x) {
    return __fdividef(1.f, 1.f + __expf(-x));
}
__device__ __forceinline__ float ftanh_(float x) {
    return 2.f * __fdividef(1.f, 1.f + __expf(-2.f * x)) - 1.f;
}

// ---------------------------------------------------------------------------
// Job descriptor (stage = 2 K64 chunks)
// ---------------------------------------------------------------------------
struct Job {
    const unsigned char *A0, *A1;   // A block bases (+mo), stride BLK; switch at K-chunk 16
    const unsigned char *Wb;        // W block base (CTA's ntile), stride 8192, contiguous
    int nst;                        // stages (K128)
    const float* biasp;
    float* cseg;
    unsigned char* hout;            // packed h buffer base
};

// W half of a stage: expect_tx(32KB) + one 16KB W bulk.  tid0 only.
__device__ __forceinline__ void issue_W_stage(const Job* jobs, int nst0, int sc,
                                              unsigned g, uint32_t sb, uint32_t mb) {
    const Job& J = jobs[sc >= nst0 ? 1 : 0];
    int ls  = (sc >= nst0) ? sc - nst0 : sc;
    int kc2 = ls * 2;
    uint32_t s    = g % NSTAGE;
    uint32_t mbar = mb + s * 8;
    MBARRIER_EXPECT_TX(mbar, 32768u);
    bulk_g2s(sb + s * STAGEB + ST_W, J.Wb + (size_t)kc2 * 8192, 16384u, mbar);
}
// A half of a stage: two 8KB bulks (blocks are BLK apart).  tid0 only.
__device__ __forceinline__ void issue_A_stage(const Job* jobs, int nst0, int sc,
                                              unsigned g, uint32_t sb, uint32_t mb) {
    const Job& J = jobs[sc >= nst0 ? 1 : 0];
    int ls  = (sc >= nst0) ? sc - nst0 : sc;
    int kc2 = ls * 2;
    const unsigned char* Ab = (kc2 < 16) ? J.A0 + (size_t)kc2 * BLK
                                         : J.A1 + (size_t)(kc2 - 16) * BLK;
    uint32_t s    = g % NSTAGE;
    uint32_t mbar = mb + s * 8;
    uint32_t dst  = sb + s * STAGEB;
    bulk_g2s(dst,        Ab,       8192u, mbar);
    bulk_g2s(dst + 8192, Ab + BLK, 8192u, mbar);
}
__device__ __forceinline__ void issue_stage(const Job* jobs, int nst0, int sc,
                                            unsigned g, uint32_t sb, uint32_t mb) {
    issue_W_stage(jobs, nst0, sc, g, sb, mb);
    issue_A_stage(jobs, nst0, sc, g, sb, mb);
}

// One K=128 stage: 2 sub-chunks x (12 LDSM + 16 HMMA) per warp.
__device__ __forceinline__ void mma_stage(uint32_t st, int wm, int wn, int lane,
                                          float acc[4][4]) {
#pragma unroll
    for (int sub = 0; sub < 2; sub++) {
        uint32_t sA = st + sub * 8192;
        uint32_t sW = st + ST_W + sub * 8192;
#pragma unroll
        for (int ks = 0; ks < 4; ks++) {
            int arow = wm * 16 + (lane & 15);
            int akb  = (ks * 16 + (lane >> 4) * 8) * 2;
            uint32_t a[4];
            ldsm4(a, sA + SWZ128(arow * 128 + akb));
#pragma unroll
            for (int nb = 0; nb < 2; nb++) {
                int brow = wn * 32 + nb * 16 + (lane & 15);
                uint32_t b[4];
                ldsm4(b, sW + SWZ128(brow * 128 + akb));
                hmma16(acc[nb * 2 + 0], a, b[0], b[2]);
                hmma16(acc[nb * 2 + 1], a, b[1], b[3]);
            }
        }
    }
}

// acc -> Sg -> gates -> cell update -> packed swizzled h write.
__device__ __forceinline__ void epilogue_cell(
    char* smem, float acc[4][4], int wm, int wn, int lane, int tid,
    const Job& J, int m0, int p0)
{
    float (*Sg)[68] = (float(*)[68])(smem + SMEM_SG);
#pragma unroll
    for (int nb = 0; nb < 2; nb++)
#pragma unroll
        for (int g = 0; g < 2; g++) {
            int f  = nb * 2 + g;
            int cc = wn * 32 + nb * 16 + g * 8 + (lane & 3) * 2;
            int rr = wm * 16 + (lane >> 2);
            Sg[rr][cc]         = acc[f][0];
            Sg[rr][cc + 1]     = acc[f][1];
            Sg[rr + 8][cc]     = acc[f][2];
            Sg[rr + 8][cc + 1] = acc[f][3];
        }
    __syncthreads();
#pragma unroll
    for (int i = 0; i < 4; i++) {
        int lin = tid + i * 256;
        int m = lin >> 4, u = lin & 15;
        int b = m0 + m;
        int col = u * 4;
        float pi_ = Sg[m][col]     + J.biasp[p0 + col];
        float pf  = Sg[m][col + 1] + J.biasp[p0 + col + 1];
        float pg  = Sg[m][col + 2] + J.biasp[p0 + col + 2];
        float po  = Sg[m][col + 3] + J.biasp[p0 + col + 3];
        int ci = m * 16 + u;
        float co = J.cseg[ci];
        float ii = fsigmoid(pi_);
        float ff = fsigmoid(pf);
        float gg = ftanh_(pg);
        float oo = fsigmoid(po);
        float cn = ff * co + ii * gg;
        float h  = oo * ftanh_(cn);
        J.cseg[ci] = cn;
        int j = (p0 >> 2) + u;
        size_t off = (size_t)(j >> 6) * BLK + SWZ128(b * 128 + (j & 63) * 2);
        *(__half*)(J.hout + off) = __float2half(h);
    }
}

// ---------------------------------------------------------------------------
// Phase: up to 2 jobs; stage ring with global stage counter gc.
// preloaded: W+expect of stages gc, gc+1 already issued pre-barrier.
// ---------------------------------------------------------------------------
__device__ void phase_exec(const Job* jobs, int njobs, bool preloaded, unsigned& gcref,
                           char* smem, uint32_t sb, uint32_t mb,
                           int tid, int wm, int wn, int lane, int m0, int p0) {
    const int nst0 = jobs[0].nst;
    const int TOT = nst0 + (njobs > 1 ? jobs[1].nst : 0);
    const unsigned gc = gcref;
    float acc[4][4];
#pragma unroll
    for (int r = 0; r < 4; r++)
#pragma unroll
        for (int c = 0; c < 4; c++) acc[r][c] = 0.f;

    if (tid == 0) {
        if (preloaded) {
            issue_A_stage(jobs, nst0, 0, gc,     sb, mb);
            issue_A_stage(jobs, nst0, 1, gc + 1, sb, mb);
        } else {
            issue_stage(jobs, nst0, 0, gc,     sb, mb);
            issue_stage(jobs, nst0, 1, gc + 1, sb, mb);
        }
    }

    for (int c = 0; c < TOT; c++) {
        unsigned g = gc + c;
        uint32_t s = g % NSTAGE;
        MBARRIER_WAIT_PARITY(mb + s * 8, (g / NSTAGE) & 1);
        // stage (g+2)%3 == (g-1)%3 was consumed last iteration (end-of-iter sync)
        if (tid == 0 && c + 2 < TOT)
            issue_stage(jobs, nst0, c + 2, g + 2, sb, mb);
        mma_stage(sb + s * STAGEB, wm, wn, lane, acc);
        if (c == nst0 - 1) {
            epilogue_cell(smem, acc, wm, wn, lane, tid, jobs[0], m0, p0);
#pragma unroll
            for (int r = 0; r < 4; r++)
#pragma unroll
                for (int cl = 0; cl < 4; cl++) acc[r][cl] = 0.f;
        } else if (c == TOT - 1) {
            epilogue_cell(smem, acc, wm, wn, lane, tid, jobs[1], m0, p0);
        }
        __syncthreads();
    }
    gcref = gc + TOT;
}

// Grid-wide barrier (tight spin)
__device__ __forceinline__ void grid_bar(unsigned target) {
    __syncthreads();
    if (threadIdx.x == 0) {
        __threadfence();
        atomicAdd(&g_bar, 1u);
        while (*(volatile unsigned int*)&g_bar < target) { }
        __threadfence();
    }
    __syncthreads();
}

// ---------------------------------------------------------------------------
// Prep kernels (pre-swizzled blocks; same layout as R10)
// ---------------------------------------------------------------------------
__global__ void pack_X_kernel(const float* __restrict__ X) {
    size_t i = (size_t)blockIdx.x * blockDim.x + threadIdx.x;
    if (i >= (size_t)Bn * Tn * DIN) return;
    int d = (int)(i % DIN);
    size_t r = i / DIN;
    int t = (int)(r % Tn), b = (int)(r / Tn);
    int kc = d >> 6, col = d & 63;
    size_t off = (size_t)(t * 8 + kc) * BLK + SWZ128(b * 128 + col * 2);
    *(__half*)(g_Xp + off) = __float2half(X[i]);
}
__global__ void pack_w0_kernel(const float* __restrict__ Wih,
                               const float* __restrict__ Whh) {
    size_t i = (size_t)blockIdx.x * blockDim.x + threadIdx.x;
    if (i >= (size_t)G4 * 1536) return;
    int p = (int)(i / 1536), k = (int)(i % 1536);
    int j = p >> 2, g4 = p & 3;
    float v = (k < Hn) ? Whh[(size_t)(g4 * Hn + j) * Hn + k]
                       : Wih[(size_t)(g4 * Hn + j) * DIN + (k - Hn)];
    int nt = p >> 6, rr = p & 63, kc = k >> 6, col = k & 63;
    size_t off = (size_t)(nt * NCH0 + kc) * 8192 + SWZ128(rr * 128 + col * 2);
    *(__half*)(g_W0p + off) = __float2half(v);
}
__global__ void pack_w1_kernel(const float* __restrict__ Wih,
                               const float* __restrict__ Whh) {
    size_t i = (size_t)blockIdx.x * blockDim.x + threadIdx.x;
    if (i >= (size_t)G4 * 2048) return;
    int p = (int)(i / 2048), k = (int)(i % 2048);
    int j = p >> 2, g4 = p & 3;
    float v = (k < Hn) ? Wih[(size_t)(g4 * Hn + j) * Hn + k]
                       : Whh[(size_t)(g4 * Hn + j) * Hn + (k - Hn)];
    int nt = p >> 6, rr = p & 63, kc = k >> 6, col = k & 63;
    size_t off = (size_t)(nt * NCH1 + kc) * 8192 + SWZ128(rr * 128 + col * 2);
    *(__half*)(g_W1p + off) = __float2half(v);
}
__global__ void pack_bias_kernel(const float* __restrict__ bi0, const float* __restrict__ bh0,
                                 const float* __restrict__ bi1, const float* __restrict__ bh1) {
    int p = blockIdx.x * blockDim.x + threadIdx.x;
    if (p >= G4) return;
    int j = p >> 2, g = p & 3;
    g_b0p[p] = bi0[g * Hn + j] + bh0[g * Hn + j];
    g_b1p[p] = bi1[g * Hn + j] + bh1[g * Hn + j];
}
__global__ void init_state_kernel() {
    size_t i = (size_t)blockIdx.x * blockDim.x + threadIdx.x;
    if (i < (size_t)16 * 16384 / 4) {
        ((uint32_t*)g_h0p[0])[i] = 0; ((uint32_t*)g_h0p[1])[i] = 0;
        ((uint32_t*)g_h1p[0])[i] = 0; ((uint32_t*)g_h1p[1])[i] = 0;
    }
    if (i == 0) g_bar = 0u;
}

// ---------------------------------------------------------------------------
// Persistent LSTM: 128 CTAs; phase = {layer1(t), layer0(t+1)}; 1 barrier/phase;
// K128 stages; W prefetched across the barrier.
// ---------------------------------------------------------------------------
__global__ __launch_bounds__(256, 1) void lstm_persistent() {
    extern __shared__ char smem[];
    uint32_t sb = smem_u32(smem);
    uint32_t mb = sb + SMEM_MB;
    const int tid = threadIdx.x, lane = tid & 31, wid = tid >> 5;
    const int wm = wid & 3, wn = wid >> 2;
    const int ntile = blockIdx.x >> 1, mh = blockIdx.x & 1;
    const int p0 = ntile * 64, m0 = mh * 64;
    float* cs0 = (float*)(smem + SMEM_CS);
    float* cs1 = cs0 + 1024;
    for (int i = tid; i < 2048; i += 256) cs0[i] = 0.f;
    if (tid == 0) {
        for (int s = 0; s < NSTAGE; s++) MBARRIER_INIT(mb + s * 8, 1);
        FENCE_PROXY_ASYNC();
    }
    __syncthreads();

    const unsigned char* W0b = g_W0p + (size_t)ntile * NCH0 * 8192;
    const unsigned char* W1b = g_W1p + (size_t)ntile * NCH1 * 8192;
    const size_t mo = (size_t)mh * 8192;

    unsigned gc = 0, bar = 0;
    Job jb[2], jbn[2];

    auto setup_phase = [&](Job* J, int t) {
        const int pc = t & 1, pn = (t + 1) & 1;
        J[0].A0 = g_h0p[pc] + mo; J[0].A1 = g_h1p[pn] + mo;
        J[0].Wb = W1b; J[0].nst = NST1;
        J[0].biasp = g_b1p; J[0].cseg = cs1; J[0].hout = g_h1p[pc];
        J[1].A0 = g_h0p[pc] + mo;
        J[1].A1 = g_Xp + (size_t)(t + 1) * 8 * BLK + mo;
        J[1].Wb = W0b; J[1].nst = NST0;
        J[1].biasp = g_b0p; J[1].cseg = cs0; J[1].hout = g_h0p[pn];
    };

    // initial layer0(0): A=[h0[1](zeros); X(0)] -> h0[0]
    jb[0].A0 = g_h0p[1] + mo; jb[0].A1 = g_Xp + mo;
    jb[0].Wb = W0b; jb[0].nst = NST0;
    jb[0].biasp = g_b0p; jb[0].cseg = cs0; jb[0].hout = g_h0p[0];
    phase_exec(jb, 1, false, gc, smem, sb, mb, tid, wm, wn, lane, m0, p0);

    setup_phase(jb, 0);
    if (tid == 0) {
        issue_W_stage(jb, jb[0].nst, 0, gc,     sb, mb);
        issue_W_stage(jb, jb[0].nst, 1, gc + 1, sb, mb);
    }
    grid_bar(++bar * NCTA);

    for (int t = 0; t < Tn - 1; t++) {
        phase_exec(jb, 2, true, gc, smem, sb, mb, tid, wm, wn, lane, m0, p0);
        if (t + 1 < Tn - 1) {
            setup_phase(jbn, t + 1);
        } else {
            // final: layer1(255): A=[h0[1]; h1[0]] -> h1[1]
            jbn[0].A0 = g_h0p[1] + mo; jbn[0].A1 = g_h1p[0] + mo;
            jbn[0].Wb = W1b; jbn[0].nst = NST1;
            jbn[0].biasp = g_b1p; jbn[0].cseg = cs1; jbn[0].hout = g_h1p[1];
        }
        if (tid == 0) {
            issue_W_stage(jbn, jbn[0].nst, 0, gc,     sb, mb);
            issue_W_stage(jbn, jbn[0].nst, 1, gc + 1, sb, mb);
        }
        grid_bar(++bar * NCTA);
        jb[0] = jbn[0]; jb[1] = jbn[1];
    }

    phase_exec(jb, 1, true, gc, smem, sb, mb, tid, wm, wn, lane, m0, p0);
}

// ---------------------------------------------------------------------------
// Final head: out[b][r] = elu(h1(255)[b] . W_br[r] + b_br[r])
// ---------------------------------------------------------------------------
__global__ void br_kernel(const float* __restrict__ Wbr,
                          const float* __restrict__ bbr,
                          float* __restrict__ out) {
    __shared__ float hs[Hn];
    const int b = blockIdx.x;
    for (int k = threadIdx.x; k < Hn; k += 256) {
        size_t off = (size_t)(k >> 6) * BLK + SWZ128(b * 128 + (k & 63) * 2);
        hs[k] = __half2float(*(const __half*)(g_h1p[1] + off));
    }
    __syncthreads();
    const int r = threadIdx.x;
    float acc = bbr[r];
    const float* w = Wbr + (size_t)r * Hn;
    for (int k = 0; k < Hn; k += 4) {
        float4 wv = *reinterpret_cast<const float4*>(w + k);
        float4 hv = *reinterpret_cast<const float4*>(&hs[k]);
        acc += wv.x * hv.x + wv.y * hv.y + wv.z * hv.z + wv.w * hv.w;
    }
    out[b * BRn + r] = acc > 0.f ? acc : expm1f(acc);
}

// ---------------------------------------------------------------------------
extern "C" void kernel_launch(void* const* d_in, const int* in_sizes, int n_in,
                              void* d_out, int out_size) {
    const float* X     = (const float*)d_in[0];
    const float* W_ih0 = (const float*)d_in[1];
    const float* W_hh0 = (const float*)d_in[2];
    const float* b_ih0 = (const float*)d_in[3];
    const float* b_hh0 = (const float*)d_in[4];
    const float* W_ih1 = (const float*)d_in[5];
    const float* W_hh1 = (const float*)d_in[6];
    const float* b_ih1 = (const float*)d_in[7];
    const float* b_hh1 = (const float*)d_in[8];
    const float* W_br  = (const float*)d_in[9];
    const float* b_br  = (const float*)d_in[10];
    float* out = (float*)d_out;

    cudaFuncSetAttribute(lstm_persistent, cudaFuncAttributeMaxDynamicSharedMemorySize,
                         SMEM_BYTES);

    pack_X_kernel<<<(Bn * Tn * DIN) / 256, 256>>>(X);
    pack_w0_kernel<<<((int)((size_t)G4 * 1536 / 256)), 256>>>(W_ih0, W_hh0);
    pack_w1_kernel<<<((int)((size_t)G4 * 2048 / 256)), 256>>>(W_ih1, W_hh1);
    pack_bias_kernel<<<G4 / 256, 256>>>(b_ih0, b_hh0, b_ih1, b_hh1);
    init_state_kernel<<<256, 256>>>();

    lstm_persistent<<<NCTA, 256, SMEM_BYTES>>>();

    br_kernel<<<Bn, 256>>>(W_br, b_br, out);
}

// round 15
// speedup vs baseline: 9.1517x; 1.0694x over previous
#include <cuda_runtime.h>
#include <cuda_fp16.h>
#include <math.h>
#include <stdint.h>

#define Bn   128
#define Tn   256
#define DIN  512
#define Hn   1024
#define G4   4096
#define BRn  256

#define NCH0 24            // K64 chunks, layer0 (h0:16, X:8)
#define NCH1 32            // K64 chunks, layer1 (h0:16, h1:16)
#define NST0 12            // K128 stages, layer0
#define NST1 16            // K128 stages, layer1

#define NSTAGE 3
#define ST_W   16384
#define STAGEB 32768
#define BLK    16384                         // A-block stride in packed arrays
#define SMEM_STAGES (NSTAGE * STAGEB)        // 98304
#define SMEM_SG  SMEM_STAGES                 // float Sg[2][64][68] = 34816
#define SMEM_CS  (SMEM_SG + 34816)           // c-state 2*64*16 f32 = 8192
#define SMEM_MB  (SMEM_CS + 8192)
#define SMEM_BYTES (SMEM_MB + 64)            // 141376
#define NCTA 128

#define SWZ128(o) ((o) ^ (((o) >> 3) & 0x70))

// ---------------------------------------------------------------------------
// Device scratch — pre-swizzled blocks (same layout as R10/R11)
// ---------------------------------------------------------------------------
__device__ __align__(1024) unsigned char g_Xp[(size_t)Tn * 8 * 16384];      // [t*8+kc][swz(b*128+col*2)]
__device__ __align__(1024) unsigned char g_W0p[(size_t)64 * NCH0 * 8192];   // [nt*NCH0+kc][swz(r*128+col*2)]
__device__ __align__(1024) unsigned char g_W1p[(size_t)64 * NCH1 * 8192];
__device__ __align__(1024) unsigned char g_h0p[2][16 * 16384];              // [jc][swz(b*128+jl*2)]
__device__ __align__(1024) unsigned char g_h1p[2][16 * 16384];
__device__ float g_b0p[G4], g_b1p[G4];
__device__ unsigned int g_bar;

// ---------------------------------------------------------------------------
// Primitives
// ---------------------------------------------------------------------------
__device__ __forceinline__ uint32_t smem_u32(const void* p) {
    uint32_t a;
    asm("{ .reg .u64 t; cvta.to.shared.u64 t, %1; cvt.u32.u64 %0, t; }"
        : "=r"(a) : "l"(p));
    return a;
}
__device__ __forceinline__ void ldsm4(uint32_t* r, uint32_t addr) {
    asm volatile("ldmatrix.sync.aligned.m8n8.x4.shared.b16 {%0,%1,%2,%3}, [%4];"
                 : "=r"(r[0]), "=r"(r[1]), "=r"(r[2]), "=r"(r[3]) : "r"(addr));
}
__device__ __forceinline__ void hmma16(float* d, const uint32_t* a, uint32_t b0, uint32_t b1) {
    asm volatile("mma.sync.aligned.m16n8k16.row.col.f32.f16.f16.f32 "
                 "{%0,%1,%2,%3}, {%4,%5,%6,%7}, {%8,%9}, {%0,%1,%2,%3};"
                 : "+f"(d[0]), "+f"(d[1]), "+f"(d[2]), "+f"(d[3])
                 : "r"(a[0]), "r"(a[1]), "r"(a[2]), "r"(a[3]), "r"(b0), "r"(b1));
}
__device__ __forceinline__ void bulk_g2s(uint32_t dst, const void* src, uint32_t bytes,
                                         uint32_t mbar) {
    asm volatile("cp.async.bulk.shared::cta.global.mbarrier::complete_tx::bytes "
                 "[%0], [%1], %2, [%3];"
                 :: "r"(dst), "l"(src), "r"(bytes), "r"(mbar) : "memory");
}
#define MBARRIER_INIT(mb, c) \
    asm volatile("mbarrier.init.shared.b64 [%0], %1;" :: "r"((uint32_t)(mb)), "r"((uint32_t)(c)) : "memory")
#define MBARRIER_EXPECT_TX(mb, tx) \
    asm volatile("mbarrier.arrive.expect_tx.shared.b64 _, [%0], %1;" :: "r"((uint32_t)(mb)), "r"((uint32_t)(tx)) : "memory")
#define FENCE_PROXY_ASYNC() asm volatile("fence.proxy.async.shared::cta;" ::: "memory")
#define MBARRIER_WAIT_PARITY(mb, par) do {                                         \
    uint32_t _mb = (uint32_t)(mb); uint32_t _p = (uint32_t)(par); uint32_t _d;     \
    asm volatile("{\n\t.reg .pred p;\n\t"                                          \
        "mbarrier.try_wait.parity.acquire.cta.shared::cta.b64 p, [%1], %2;\n\t"    \
        "selp.b32 %0, 1, 0, p;\n\t}" : "=r"(_d) : "r"(_mb), "r"(_p) : "memory");   \
    if (!_d) {                                                                     \
        asm volatile("{\n\t.reg .pred P1;\n\t"                                     \
            "WL_%=:\n\t"                                                           \
            "mbarrier.try_wait.parity.acquire.cta.shared::cta.b64 P1, [%0], %1, 0x989680;\n\t" \
            "@P1 bra.uni WD_%=;\n\t"                                               \
            "bra.uni WL_%=;\n\t"                                                   \
            "WD_%=:\n\t}" :: "r"(_mb), "r"(_p) : "memory");                        \
    }                                                                              \
} while (0)

__device__ __forceinline__ float fsigmoid(float x) {
    return __fdividef(1.f, 1.f + __expf(-x));
}
__device__ __forceinline__ float ftanh_(float x) {
    return 2.f * __fdividef(1.f, 1.f + __expf(-2.f * x)) - 1.f;
}

// ---------------------------------------------------------------------------
// Job descriptor (stage = 2 K64 chunks)
// ---------------------------------------------------------------------------
struct Job {
    const unsigned char *A0, *A1;   // A block bases (+mo), stride BLK; switch at K-chunk 16
    const unsigned char *Wb;        // W block base (CTA's ntile), stride 8192, contiguous
    int nst;                        // stages (K128)
    const float* biasp;
    float* cseg;
    unsigned char* hout;            // packed h buffer base
};

// W half of a stage: expect_tx(32KB) + one 16KB W bulk.  tid0 only.
__device__ __forceinline__ void issue_W_stage(const Job* jobs, int nst0, int sc,
                                              unsigned g, uint32_t sb, uint32_t mb) {
    const Job& J = jobs[sc >= nst0 ? 1 : 0];
    int ls  = (sc >= nst0) ? sc - nst0 : sc;
    int kc2 = ls * 2;
    uint32_t s    = g % NSTAGE;
    uint32_t mbar = mb + s * 8;
    MBARRIER_EXPECT_TX(mbar, 32768u);
    bulk_g2s(sb + s * STAGEB + ST_W, J.Wb + (size_t)kc2 * 8192, 16384u, mbar);
}
// A half of a stage: two 8KB bulks (blocks are BLK apart).  tid0 only.
__device__ __forceinline__ void issue_A_stage(const Job* jobs, int nst0, int sc,
                                              unsigned g, uint32_t sb, uint32_t mb) {
    const Job& J = jobs[sc >= nst0 ? 1 : 0];
    int ls  = (sc >= nst0) ? sc - nst0 : sc;
    int kc2 = ls * 2;
    const unsigned char* Ab = (kc2 < 16) ? J.A0 + (size_t)kc2 * BLK
                                         : J.A1 + (size_t)(kc2 - 16) * BLK;
    uint32_t s    = g % NSTAGE;
    uint32_t mbar = mb + s * 8;
    uint32_t dst  = sb + s * STAGEB;
    bulk_g2s(dst,        Ab,       8192u, mbar);
    bulk_g2s(dst + 8192, Ab + BLK, 8192u, mbar);
}
__device__ __forceinline__ void issue_stage(const Job* jobs, int nst0, int sc,
                                            unsigned g, uint32_t sb, uint32_t mb) {
    issue_W_stage(jobs, nst0, sc, g, sb, mb);
    issue_A_stage(jobs, nst0, sc, g, sb, mb);
}

// One K=128 stage, K-split tiling: warp (wg, wm, wn) covers output rows
// [wm*32,+32) x cols [wn*32,+32), accumulating K-half wg of each K64 chunk.
// Per warp per K64 chunk: 4 A-LDSM + 4 W-LDSM + 16 HMMA.
__device__ __forceinline__ void mma_stage(uint32_t st, int wg, int wm, int wn, int lane,
                                          float acc[2][4][4]) {
#pragma unroll
    for (int sub = 0; sub < 2; sub++) {
        uint32_t sA = st + sub * 8192;
        uint32_t sW = st + ST_W + sub * 8192;
#pragma unroll
        for (int k16 = 0; k16 < 2; k16++) {
            int akb = (wg * 32 + k16 * 16 + (lane >> 4) * 8) * 2;
            uint32_t a[2][4];
#pragma unroll
            for (int mt = 0; mt < 2; mt++) {
                int arow = wm * 32 + mt * 16 + (lane & 15);
                ldsm4(a[mt], sA + SWZ128(arow * 128 + akb));
            }
#pragma unroll
            for (int nb = 0; nb < 2; nb++) {
                int brow = wn * 32 + nb * 16 + (lane & 15);
                uint32_t b[4];
                ldsm4(b, sW + SWZ128(brow * 128 + akb));
#pragma unroll
                for (int mt = 0; mt < 2; mt++) {
                    hmma16(acc[mt][nb * 2 + 0], a[mt], b[0], b[2]);
                    hmma16(acc[mt][nb * 2 + 1], a[mt], b[1], b[3]);
                }
            }
        }
    }
}

// acc -> Sg[wg] -> sum K-groups -> gates -> cell update -> packed h write.
__device__ __forceinline__ void epilogue_cell(
    char* smem, float acc[2][4][4], int wg, int wm, int wn, int lane, int tid,
    const Job& J, int m0, int p0)
{
    float (*Sg)[64][68] = (float(*)[64][68])(smem + SMEM_SG);
#pragma unroll
    for (int mt = 0; mt < 2; mt++)
#pragma unroll
        for (int nb = 0; nb < 2; nb++)
#pragma unroll
            for (int g = 0; g < 2; g++) {
                int f  = nb * 2 + g;
                int cc = wn * 32 + nb * 16 + g * 8 + (lane & 3) * 2;
                int rr = wm * 32 + mt * 16 + (lane >> 2);
                Sg[wg][rr][cc]         = acc[mt][f][0];
                Sg[wg][rr][cc + 1]     = acc[mt][f][1];
                Sg[wg][rr + 8][cc]     = acc[mt][f][2];
                Sg[wg][rr + 8][cc + 1] = acc[mt][f][3];
            }
    __syncthreads();
#pragma unroll
    for (int i = 0; i < 4; i++) {
        int lin = tid + i * 256;
        int m = lin >> 4, u = lin & 15;
        int b = m0 + m;
        int col = u * 4;
        float pi_ = Sg[0][m][col]     + Sg[1][m][col]     + J.biasp[p0 + col];
        float pf  = Sg[0][m][col + 1] + Sg[1][m][col + 1] + J.biasp[p0 + col + 1];
        float pg  = Sg[0][m][col + 2] + Sg[1][m][col + 2] + J.biasp[p0 + col + 2];
        float po  = Sg[0][m][col + 3] + Sg[1][m][col + 3] + J.biasp[p0 + col + 3];
        int ci = m * 16 + u;
        float co = J.cseg[ci];
        float ii = fsigmoid(pi_);
        float ff = fsigmoid(pf);
        float gg = ftanh_(pg);
        float oo = fsigmoid(po);
        float cn = ff * co + ii * gg;
        float h  = oo * ftanh_(cn);
        J.cseg[ci] = cn;
        int j = (p0 >> 2) + u;
        size_t off = (size_t)(j >> 6) * BLK + SWZ128(b * 128 + (j & 63) * 2);
        *(__half*)(J.hout + off) = __float2half(h);
    }
}

// ---------------------------------------------------------------------------
// Phase: up to 2 jobs; stage ring with global stage counter gc.
// preloaded: W+expect of stages gc, gc+1 already issued pre-barrier.
// ---------------------------------------------------------------------------
__device__ void phase_exec(const Job* jobs, int njobs, bool preloaded, unsigned& gcref,
                           char* smem, uint32_t sb, uint32_t mb,
                           int tid, int wg, int wm, int wn, int lane, int m0, int p0) {
    const int nst0 = jobs[0].nst;
    const int TOT = nst0 + (njobs > 1 ? jobs[1].nst : 0);
    const unsigned gc = gcref;
    float acc[2][4][4];
#pragma unroll
    for (int mt = 0; mt < 2; mt++)
#pragma unroll
        for (int r = 0; r < 4; r++)
#pragma unroll
            for (int c = 0; c < 4; c++) acc[mt][r][c] = 0.f;

    if (tid == 0) {
        if (preloaded) {
            issue_A_stage(jobs, nst0, 0, gc,     sb, mb);
            issue_A_stage(jobs, nst0, 1, gc + 1, sb, mb);
        } else {
            issue_stage(jobs, nst0, 0, gc,     sb, mb);
            issue_stage(jobs, nst0, 1, gc + 1, sb, mb);
        }
    }

    for (int c = 0; c < TOT; c++) {
        unsigned g = gc + c;
        uint32_t s = g % NSTAGE;
        MBARRIER_WAIT_PARITY(mb + s * 8, (g / NSTAGE) & 1);
        if (tid == 0 && c + 2 < TOT)
            issue_stage(jobs, nst0, c + 2, g + 2, sb, mb);
        mma_stage(sb + s * STAGEB, wg, wm, wn, lane, acc);
        if (c == nst0 - 1) {
            epilogue_cell(smem, acc, wg, wm, wn, lane, tid, jobs[0], m0, p0);
#pragma unroll
            for (int mt = 0; mt < 2; mt++)
#pragma unroll
                for (int r = 0; r < 4; r++)
#pragma unroll
                    for (int cl = 0; cl < 4; cl++) acc[mt][r][cl] = 0.f;
        } else if (c == TOT - 1) {
            epilogue_cell(smem, acc, wg, wm, wn, lane, tid, jobs[1], m0, p0);
        }
        __syncthreads();
    }
    gcref = gc + TOT;
}

// Grid-wide barrier (tight spin)
__device__ __forceinline__ void grid_bar(unsigned target) {
    __syncthreads();
    if (threadIdx.x == 0) {
        __threadfence();
        atomicAdd(&g_bar, 1u);
        while (*(volatile unsigned int*)&g_bar < target) { }
        __threadfence();
    }
    __syncthreads();
}

// ---------------------------------------------------------------------------
// Prep kernels (pre-swizzled blocks)
// ---------------------------------------------------------------------------
__global__ void pack_X_kernel(const float* __restrict__ X) {
    size_t i = (size_t)blockIdx.x * blockDim.x + threadIdx.x;
    if (i >= (size_t)Bn * Tn * DIN) return;
    int d = (int)(i % DIN);
    size_t r = i / DIN;
    int t = (int)(r % Tn), b = (int)(r / Tn);
    int kc = d >> 6, col = d & 63;
    size_t off = (size_t)(t * 8 + kc) * BLK + SWZ128(b * 128 + col * 2);
    *(__half*)(g_Xp + off) = __float2half(X[i]);
}
__global__ void pack_w0_kernel(const float* __restrict__ Wih,
                               const float* __restrict__ Whh) {
    size_t i = (size_t)blockIdx.x * blockDim.x + threadIdx.x;
    if (i >= (size_t)G4 * 1536) return;
    int p = (int)(i / 1536), k = (int)(i % 1536);
    int j = p >> 2, g4 = p & 3;
    float v = (k < Hn) ? Whh[(size_t)(g4 * Hn + j) * Hn + k]
                       : Wih[(size_t)(g4 * Hn + j) * DIN + (k - Hn)];
    int nt = p >> 6, rr = p & 63, kc = k >> 6, col = k & 63;
    size_t off = (size_t)(nt * NCH0 + kc) * 8192 + SWZ128(rr * 128 + col * 2);
    *(__half*)(g_W0p + off) = __float2half(v);
}
__global__ void pack_w1_kernel(const float* __restrict__ Wih,
                               const float* __restrict__ Whh) {
    size_t i = (size_t)blockIdx.x * blockDim.x + threadIdx.x;
    if (i >= (size_t)G4 * 2048) return;
    int p = (int)(i / 2048), k = (int)(i % 2048);
    int j = p >> 2, g4 = p & 3;
    float v = (k < Hn) ? Wih[(size_t)(g4 * Hn + j) * Hn + k]
                       : Whh[(size_t)(g4 * Hn + j) * Hn + (k - Hn)];
    int nt = p >> 6, rr = p & 63, kc = k >> 6, col = k & 63;
    size_t off = (size_t)(nt * NCH1 + kc) * 8192 + SWZ128(rr * 128 + col * 2);
    *(__half*)(g_W1p + off) = __float2half(v);
}
__global__ void pack_bias_kernel(const float* __restrict__ bi0, const float* __restrict__ bh0,
                                 const float* __restrict__ bi1, const float* __restrict__ bh1) {
    int p = blockIdx.x * blockDim.x + threadIdx.x;
    if (p >= G4) return;
    int j = p >> 2, g = p & 3;
    g_b0p[p] = bi0[g * Hn + j] + bh0[g * Hn + j];
    g_b1p[p] = bi1[g * Hn + j] + bh1[g * Hn + j];
}
__global__ void init_state_kernel() {
    size_t i = (size_t)blockIdx.x * blockDim.x + threadIdx.x;
    if (i < (size_t)16 * 16384 / 4) {
        ((uint32_t*)g_h0p[0])[i] = 0; ((uint32_t*)g_h0p[1])[i] = 0;
        ((uint32_t*)g_h1p[0])[i] = 0; ((uint32_t*)g_h1p[1])[i] = 0;
    }
    if (i == 0) g_bar = 0u;
}

// ---------------------------------------------------------------------------
// Persistent LSTM: 128 CTAs; phase = {layer1(t), layer0(t+1)}; 1 barrier/phase;
// K128 stages; K-split 32x32 warp tiles; W prefetched across the barrier.
// ---------------------------------------------------------------------------
__global__ __launch_bounds__(256, 1) void lstm_persistent() {
    extern __shared__ char smem[];
    uint32_t sb = smem_u32(smem);
    uint32_t mb = sb + SMEM_MB;
    const int tid = threadIdx.x, lane = tid & 31, wid = tid >> 5;
    const int wg = wid >> 2;           // K-group (0/1)
    const int wq = wid & 3;
    const int wm = wq & 1, wn = wq >> 1;   // 32x32 output quadrant
    const int ntile = blockIdx.x >> 1, mh = blockIdx.x & 1;
    const int p0 = ntile * 64, m0 = mh * 64;
    float* cs0 = (float*)(smem + SMEM_CS);
    float* cs1 = cs0 + 1024;
    for (int i = tid; i < 2048; i += 256) cs0[i] = 0.f;
    if (tid == 0) {
        for (int s = 0; s < NSTAGE; s++) MBARRIER_INIT(mb + s * 8, 1);
        FENCE_PROXY_ASYNC();
    }
    __syncthreads();

    const unsigned char* W0b = g_W0p + (size_t)ntile * NCH0 * 8192;
    const unsigned char* W1b = g_W1p + (size_t)ntile * NCH1 * 8192;
    const size_t mo = (size_t)mh * 8192;

    unsigned gc = 0, bar = 0;
    Job jb[2], jbn[2];

    auto setup_phase = [&](Job* J, int t) {
        const int pc = t & 1, pn = (t + 1) & 1;
        J[0].A0 = g_h0p[pc] + mo; J[0].A1 = g_h1p[pn] + mo;
        J[0].Wb = W1b; J[0].nst = NST1;
        J[0].biasp = g_b1p; J[0].cseg = cs1; J[0].hout = g_h1p[pc];
        J[1].A0 = g_h0p[pc] + mo;
        J[1].A1 = g_Xp + (size_t)(t + 1) * 8 * BLK + mo;
        J[1].Wb = W0b; J[1].nst = NST0;
        J[1].biasp = g_b0p; J[1].cseg = cs0; J[1].hout = g_h0p[pn];
    };

    // initial layer0(0): A=[h0[1](zeros); X(0)] -> h0[0]
    jb[0].A0 = g_h0p[1] + mo; jb[0].A1 = g_Xp + mo;
    jb[0].Wb = W0b; jb[0].nst = NST0;
    jb[0].biasp = g_b0p; jb[0].cseg = cs0; jb[0].hout = g_h0p[0];
    phase_exec(jb, 1, false, gc, smem, sb, mb, tid, wg, wm, wn, lane, m0, p0);

    setup_phase(jb, 0);
    if (tid == 0) {
        issue_W_stage(jb, jb[0].nst, 0, gc,     sb, mb);
        issue_W_stage(jb, jb[0].nst, 1, gc + 1, sb, mb);
    }
    grid_bar(++bar * NCTA);

    for (int t = 0; t < Tn - 1; t++) {
        phase_exec(jb, 2, true, gc, smem, sb, mb, tid, wg, wm, wn, lane, m0, p0);
        if (t + 1 < Tn - 1) {
            setup_phase(jbn, t + 1);
        } else {
            // final: layer1(255): A=[h0[1]; h1[0]] -> h1[1]
            jbn[0].A0 = g_h0p[1] + mo; jbn[0].A1 = g_h1p[0] + mo;
            jbn[0].Wb = W1b; jbn[0].nst = NST1;
            jbn[0].biasp = g_b1p; jbn[0].cseg = cs1; jbn[0].hout = g_h1p[1];
        }
        if (tid == 0) {
            issue_W_stage(jbn, jbn[0].nst, 0, gc,     sb, mb);
            issue_W_stage(jbn, jbn[0].nst, 1, gc + 1, sb, mb);
        }
        grid_bar(++bar * NCTA);
        jb[0] = jbn[0]; jb[1] = jbn[1];
    }

    phase_exec(jb, 1, true, gc, smem, sb, mb, tid, wg, wm, wn, lane, m0, p0);
}

// ---------------------------------------------------------------------------
// Final head: out[b][r] = elu(h1(255)[b] . W_br[r] + b_br[r])
// ---------------------------------------------------------------------------
__global__ void br_kernel(const float* __restrict__ Wbr,
                          const float* __restrict__ bbr,
                          float* __restrict__ out) {
    __shared__ float hs[Hn];
    const int b = blockIdx.x;
    for (int k = threadIdx.x; k < Hn; k += 256) {
        size_t off = (size_t)(k >> 6) * BLK + SWZ128(b * 128 + (k & 63) * 2);
        hs[k] = __half2float(*(const __half*)(g_h1p[1] + off));
    }
    __syncthreads();
    const int r = threadIdx.x;
    float acc = bbr[r];
    const float* w = Wbr + (size_t)r * Hn;
    for (int k = 0; k < Hn; k += 4) {
        float4 wv = *reinterpret_cast<const float4*>(w + k);
        float4 hv = *reinterpret_cast<const float4*>(&hs[k]);
        acc += wv.x * hv.x + wv.y * hv.y + wv.z * hv.z + wv.w * hv.w;
    }
    out[b * BRn + r] = acc > 0.f ? acc : expm1f(acc);
}

// ---------------------------------------------------------------------------
extern "C" void kernel_launch(void* const* d_in, const int* in_sizes, int n_in,
                              void* d_out, int out_size) {
    const float* X     = (const float*)d_in[0];
    const float* W_ih0 = (const float*)d_in[1];
    const float* W_hh0 = (const float*)d_in[2];
    const float* b_ih0 = (const float*)d_in[3];
    const float* b_hh0 = (const float*)d_in[4];
    const float* W_ih1 = (const float*)d_in[5];
    const float* W_hh1 = (const float*)d_in[6];
    const float* b_ih1 = (const float*)d_in[7];
    const float* b_hh1 = (const float*)d_in[8];
    const float* W_br  = (const float*)d_in[9];
    const float* b_br  = (const float*)d_in[10];
    float* out = (float*)d_out;

    cudaFuncSetAttribute(lstm_persistent, cudaFuncAttributeMaxDynamicSharedMemorySize,
                         SMEM_BYTES);

    pack_X_kernel<<<(Bn * Tn * DIN) / 256, 256>>>(X);
    pack_w0_kernel<<<((int)((size_t)G4 * 1536 / 256)), 256>>>(W_ih0, W_hh0);
    pack_w1_kernel<<<((int)((size_t)G4 * 2048 / 256)), 256>>>(W_ih1, W_hh1);
    pack_bias_kernel<<<G4 / 256, 256>>>(b_ih0, b_hh0, b_ih1, b_hh1);
    init_state_kernel<<<256, 256>>>();

    lstm_persistent<<<NCTA, 256, SMEM_BYTES>>>();

    br_kernel<<<Bn, 256>>>(W_br, b_br, out);
}